// round 1
// baseline (speedup 1.0000x reference)
#include <cuda_runtime.h>
#include <math.h>

// Problem constants
#define Bq   2
#define Sq   2048
#define DIMq 2048
#define Hq   16
#define DKq  128
#define DRq  64
#define DCq  512
#define DCPq 1024
#define DVq  128
#define DQK  192           // DK + DR
#define Mrows (Bq*Sq)      // 4096

// ---------------- scratch (allocation-free: __device__ bss) ----------------
__device__ float g_c [Mrows * DCq];                    //  8 MB
__device__ float g_cp[Mrows * DCPq];                   // 16 MB
__device__ float g_kr[Mrows * DRq];                    //  1 MB
__device__ float g_q [(size_t)Bq*Hq*Sq*DQK];           // 50 MB [B,H,S,192]
__device__ float g_k [(size_t)Bq*Hq*Sq*DQK];           // 50 MB [B,H,S,192]
__device__ float g_v [(size_t)Bq*Hq*Sq*DVq];           // 33 MB [B,H,S,128]

// ---------------------------------------------------------------------------
// Generic fp32 GEMM: C = A[M,K] @ B[K,N], row-major. Tile 128x64x16,
// 256 threads, 8x4 per-thread microtile. A staged k-major with XOR swizzle
// so compute-side LDS are conflict-free float4.
// mode==0: C[r*out_ld + col_off + n]
// mode==1: per-head (blockIdx.z = h), weights [H,K,N],
//          C[((b*H+h)*S + s)*out_ld + col_off + n], r = b*S + s
// ---------------------------------------------------------------------------
__global__ __launch_bounds__(256)
void gemm_k(const float* __restrict__ A, const float* __restrict__ Bw,
            float* __restrict__ C, int N, int K, int mode, int col_off, int out_ld)
{
    __shared__ __align__(16) float As[16][128];   // [k][m], m swizzled
    __shared__ __align__(16) float Bs[16][64];    // [k][n]

    const int tid = threadIdx.x;
    const int tx = tid & 15, ty = tid >> 4;
    const int m_blk = blockIdx.y * 128;
    const int n_blk = blockIdx.x * 64;
    if (mode) Bw += (size_t)blockIdx.z * (size_t)K * (size_t)N;

    float acc[8][4];
#pragma unroll
    for (int i = 0; i < 8; i++)
#pragma unroll
        for (int j = 0; j < 4; j++) acc[i][j] = 0.f;

    for (int kt = 0; kt < K; kt += 16) {
#pragma unroll
        for (int i = 0; i < 8; i++) {
            int e = tid + i * 256;
            int m = e >> 4, k = e & 15;
            As[k][m ^ (k << 2)] = A[(size_t)(m_blk + m) * K + kt + k];
        }
#pragma unroll
        for (int i = 0; i < 4; i++) {
            int e = tid + i * 256;
            int k = e >> 6, n = e & 63;
            Bs[k][n] = Bw[(size_t)(kt + k) * N + n_blk + n];
        }
        __syncthreads();
#pragma unroll
        for (int kk = 0; kk < 16; kk++) {
            const int swz = kk << 2;
            float4 a0 = *(const float4*)&As[kk][(ty * 8)     ^ swz];
            float4 a1 = *(const float4*)&As[kk][(ty * 8 + 4) ^ swz];
            float4 bv = *(const float4*)&Bs[kk][tx * 4];
            float av[8] = {a0.x, a0.y, a0.z, a0.w, a1.x, a1.y, a1.z, a1.w};
            float bb[4] = {bv.x, bv.y, bv.z, bv.w};
#pragma unroll
            for (int i = 0; i < 8; i++)
#pragma unroll
                for (int j = 0; j < 4; j++)
                    acc[i][j] = fmaf(av[i], bb[j], acc[i][j]);
        }
        __syncthreads();
    }

#pragma unroll
    for (int i = 0; i < 8; i++) {
        int m = m_blk + ty * 8 + i;
        size_t rowbase;
        if (mode == 0) {
            rowbase = (size_t)m * (size_t)out_ld;
        } else {
            int b = m >> 11, s = m & 2047;
            rowbase = ((size_t)(b * Hq + blockIdx.z) * Sq + s) * (size_t)out_ld;
        }
        float4 o = make_float4(acc[i][0], acc[i][1], acc[i][2], acc[i][3]);
        *(float4*)&C[rowbase + col_off + n_blk + tx * 4] = o;
    }
}

// ---------------------------------------------------------------------------
// Broadcast k_r[B,S,64] into g_k[B,H,S,192] columns [128,192)
// ---------------------------------------------------------------------------
__global__ __launch_bounds__(256)
void bcast_k(const float* __restrict__ kr, float* __restrict__ K)
{
    int idx = blockIdx.x * 256 + threadIdx.x;   // < 2^22
    int j = idx & 63;
    int s = (idx >> 6) & 2047;
    int h = (idx >> 17) & 15;
    int b = idx >> 21;
    K[((size_t)((b * Hq + h) * Sq + s)) * DQK + DKq + j] =
        kr[((size_t)(b * Sq + s)) * DRq + j];
}

// ---------------------------------------------------------------------------
// Causal flash attention. grid (S/64, B*H), 256 threads.
// 64 queries x 64 keys per tile, D=192, DV=128, online softmax.
// Q/K staged d-major [192][64] with XOR swizzle (conflict-free float4 reads),
// V [64][128], P [64][68]. 148480 B dynamic smem -> 1 CTA/SM.
// ---------------------------------------------------------------------------
__global__ __launch_bounds__(256)
void attn_k(const float* __restrict__ Q, const float* __restrict__ Kt,
            const float* __restrict__ V, float* __restrict__ O)
{
    extern __shared__ __align__(16) float sm[];
    float* Qs = sm;                   // 192*64
    float* Ks = Qs + 192 * 64;        // 192*64
    float* Vs = Ks + 192 * 64;        // 64*128
    float* Ps = Vs + 64 * 128;        // 64*68

    const int bh = blockIdx.y;
    const int b = bh >> 4, h = bh & 15;
    const size_t qkbase = (size_t)bh * Sq * DQK;
    const size_t vbase  = (size_t)bh * Sq * DVq;
    const int s0 = blockIdx.x * 64;
    const int tid = threadIdx.x, tx = tid & 15, ty = tid >> 4;

    // load Q tile (transposed + swizzled)
#pragma unroll 4
    for (int e = tid; e < 64 * 192; e += 256) {
        int r = e / 192, d = e - r * 192;
        Qs[d * 64 + (r ^ ((d & 15) << 2))] = Q[qkbase + (size_t)(s0 + r) * DQK + d];
    }

    float m_i[4], l_i[4], acc[4][8];
#pragma unroll
    for (int i = 0; i < 4; i++) {
        m_i[i] = -INFINITY; l_i[i] = 0.f;
#pragma unroll
        for (int j = 0; j < 8; j++) acc[i][j] = 0.f;
    }

    const float scale = 0.07216878364870322f;   // 1/sqrt(192)
    const int jmax = blockIdx.x;

    for (int jb = 0; jb <= jmax; jb++) {
        __syncthreads();   // previous PV done (also orders first Q load)
#pragma unroll 4
        for (int e = tid; e < 64 * 192; e += 256) {
            int r = e / 192, d = e - r * 192;
            Ks[d * 64 + (r ^ ((d & 15) << 2))] =
                Kt[qkbase + (size_t)(jb * 64 + r) * DQK + d];
        }
#pragma unroll 4
        for (int e = tid; e < 64 * 128; e += 256) {
            int t = e >> 7, c = e & 127;
            Vs[e] = V[vbase + (size_t)(jb * 64 + t) * DVq + c];
        }
        __syncthreads();

        // ---- scores: 4x4 microtile over D=192 ----
        float sc[4][4];
#pragma unroll
        for (int i = 0; i < 4; i++)
#pragma unroll
            for (int j = 0; j < 4; j++) sc[i][j] = 0.f;

#pragma unroll 16
        for (int kk = 0; kk < 192; kk++) {
            const int swz = (kk & 15) << 2;
            float4 qv = *(const float4*)&Qs[kk * 64 + ((ty * 4) ^ swz)];
            float4 kv = *(const float4*)&Ks[kk * 64 + ((tx * 4) ^ swz)];
            float qa[4] = {qv.x, qv.y, qv.z, qv.w};
            float ka[4] = {kv.x, kv.y, kv.z, kv.w};
#pragma unroll
            for (int i = 0; i < 4; i++)
#pragma unroll
                for (int j = 0; j < 4; j++)
                    sc[i][j] = fmaf(qa[i], ka[j], sc[i][j]);
        }

        // ---- scale + causal mask (only diagonal block needs masking) ----
        const bool diag = (jb == jmax);
#pragma unroll
        for (int i = 0; i < 4; i++) {
            int row = s0 + ty * 4 + i;
#pragma unroll
            for (int j = 0; j < 4; j++) {
                float v = sc[i][j] * scale;
                if (diag && (jb * 64 + tx * 4 + j) > row) v = -INFINITY;
                sc[i][j] = v;
            }
        }

        // ---- online softmax ----
#pragma unroll
        for (int i = 0; i < 4; i++) {
            float rm = fmaxf(fmaxf(sc[i][0], sc[i][1]), fmaxf(sc[i][2], sc[i][3]));
#pragma unroll
            for (int o = 8; o > 0; o >>= 1)
                rm = fmaxf(rm, __shfl_xor_sync(0xffffffffu, rm, o, 16));
            float mnew = fmaxf(m_i[i], rm);
            float alpha = __expf(m_i[i] - mnew);
            m_i[i] = mnew;
            float p0 = __expf(sc[i][0] - mnew);
            float p1 = __expf(sc[i][1] - mnew);
            float p2 = __expf(sc[i][2] - mnew);
            float p3 = __expf(sc[i][3] - mnew);
            float rs = p0 + p1 + p2 + p3;
#pragma unroll
            for (int o = 8; o > 0; o >>= 1)
                rs += __shfl_xor_sync(0xffffffffu, rs, o, 16);
            l_i[i] = l_i[i] * alpha + rs;
            *(float4*)&Ps[(ty * 4 + i) * 68 + tx * 4] = make_float4(p0, p1, p2, p3);
#pragma unroll
            for (int j = 0; j < 8; j++) acc[i][j] *= alpha;
        }
        __syncthreads();   // Ps visible to all

        // ---- PV: acc[4 rows][8 cols] += P[64] x V[64][128] ----
#pragma unroll 4
        for (int t = 0; t < 64; t++) {
            float4 v0 = *(const float4*)&Vs[t * 128 + tx * 8];
            float4 v1 = *(const float4*)&Vs[t * 128 + tx * 8 + 4];
#pragma unroll
            for (int i = 0; i < 4; i++) {
                float p = Ps[(ty * 4 + i) * 68 + t];
                acc[i][0] = fmaf(p, v0.x, acc[i][0]);
                acc[i][1] = fmaf(p, v0.y, acc[i][1]);
                acc[i][2] = fmaf(p, v0.z, acc[i][2]);
                acc[i][3] = fmaf(p, v0.w, acc[i][3]);
                acc[i][4] = fmaf(p, v1.x, acc[i][4]);
                acc[i][5] = fmaf(p, v1.y, acc[i][5]);
                acc[i][6] = fmaf(p, v1.z, acc[i][6]);
                acc[i][7] = fmaf(p, v1.w, acc[i][7]);
            }
        }
    }

    // ---- epilogue: out[b, s, h*128 + c] ----
#pragma unroll
    for (int i = 0; i < 4; i++) {
        int s = s0 + ty * 4 + i;
        float inv = 1.0f / l_i[i];
        size_t o = ((size_t)(b * Sq + s)) * (size_t)(Hq * DVq) + h * DVq + tx * 8;
        float4 o0 = make_float4(acc[i][0]*inv, acc[i][1]*inv, acc[i][2]*inv, acc[i][3]*inv);
        float4 o1 = make_float4(acc[i][4]*inv, acc[i][5]*inv, acc[i][6]*inv, acc[i][7]*inv);
        *(float4*)&O[o]     = o0;
        *(float4*)&O[o + 4] = o1;
    }
}

// ---------------------------------------------------------------------------
extern "C" void kernel_launch(void* const* d_in, const int* in_sizes, int n_in,
                              void* d_out, int out_size)
{
    (void)in_sizes; (void)n_in; (void)out_size;
    const float* x    = (const float*)d_in[0];
    const float* W_c  = (const float*)d_in[1];
    const float* W_cp = (const float*)d_in[2];
    const float* W_qc = (const float*)d_in[3];
    const float* W_qr = (const float*)d_in[4];
    const float* W_kc = (const float*)d_in[5];
    const float* W_kr = (const float*)d_in[6];
    const float* W_v  = (const float*)d_in[7];
    float* out = (float*)d_out;

    float *c_buf, *cp_buf, *kr_buf, *q_buf, *k_buf, *v_buf;
    cudaGetSymbolAddress((void**)&c_buf,  g_c);
    cudaGetSymbolAddress((void**)&cp_buf, g_cp);
    cudaGetSymbolAddress((void**)&kr_buf, g_kr);
    cudaGetSymbolAddress((void**)&q_buf,  g_q);
    cudaGetSymbolAddress((void**)&k_buf,  g_k);
    cudaGetSymbolAddress((void**)&v_buf,  g_v);

    const int ATTN_SMEM = (192*64 + 192*64 + 64*128 + 64*68) * (int)sizeof(float); // 148480
    cudaFuncSetAttribute(attn_k, cudaFuncAttributeMaxDynamicSharedMemorySize, ATTN_SMEM);

    // latent compressions + shared rotary key
    gemm_k<<<dim3( 8, 32, 1), 256>>>(x, W_c,  c_buf,  512, 2048, 0, 0, 512);
    gemm_k<<<dim3(16, 32, 1), 256>>>(x, W_cp, cp_buf, 1024, 2048, 0, 0, 1024);
    gemm_k<<<dim3( 1, 32, 1), 256>>>(x, W_kr, kr_buf,   64, 2048, 0, 0, 64);

    // per-head projections (batched over blockIdx.z = h)
    gemm_k<<<dim3( 2, 32, Hq), 256>>>(cp_buf, W_qc, q_buf, 128, 1024, 1, 0,   DQK);
    gemm_k<<<dim3( 1, 32, Hq), 256>>>(cp_buf, W_qr, q_buf,  64, 1024, 1, 128, DQK);
    gemm_k<<<dim3( 2, 32, Hq), 256>>>(c_buf,  W_kc, k_buf, 128,  512, 1, 0,   DQK);
    gemm_k<<<dim3( 2, 32, Hq), 256>>>(c_buf,  W_v,  v_buf, 128,  512, 1, 0,   DVq);

    // broadcast k_r across heads into K[..., 128:192)
    bcast_k<<<(Bq*Hq*Sq*DRq) / 256, 256>>>(kr_buf, k_buf);

    // causal flash attention
    attn_k<<<dim3(Sq / 64, Bq * Hq), 256, ATTN_SMEM>>>(q_buf, k_buf, v_buf, out);
}

// round 3
// speedup vs baseline: 1.3487x; 1.3487x over previous
#include <cuda_runtime.h>
#include <cuda_bf16.h>
#include <math.h>
#include <stdint.h>

// Problem constants
#define Bq   2
#define Sq   2048
#define DIMq 2048
#define Hq   16
#define DKq  128
#define DRq  64
#define DCq  512
#define DCPq 1024
#define DVq  128
#define DQK  192
#define Mrows (Bq*Sq)      // 4096

// ------------------------- scratch arena (bss) ------------------------------
#define O_XHI    0ULL
#define O_XLO    16777216ULL
#define O_WCTH   33554432ULL
#define O_WCTL   35651584ULL
#define O_WCPTH  37748736ULL
#define O_WCPTL  41943040ULL
#define O_WQCTH  46137344ULL
#define O_WQCTL  50331648ULL
#define O_WQRTH  54525952ULL
#define O_WQRTL  56623104ULL
#define O_WKCTH  58720256ULL
#define O_WKCTL  60817408ULL
#define O_WKRTH  62914560ULL
#define O_WKRTL  63176704ULL
#define O_WVTH   63438848ULL
#define O_WVTL   65536000ULL
#define O_CHI    67633152ULL
#define O_CLO    71827456ULL
#define O_CPHI   76021760ULL
#define O_CPLO   84410368ULL
#define O_KR     92798976ULL
#define O_Q      93847552ULL
#define O_K      144179200ULL
#define O_V      194510848ULL
#define ARENA_BYTES 228065280ULL

__device__ __align__(256) char g_arena[ARENA_BYTES];

// ------------------------- helpers ------------------------------------------
__device__ __forceinline__ uint32_t smem_u32(const void* p) {
    uint32_t a;
    asm("{ .reg .u64 t; cvta.to.shared.u64 t, %1; cvt.u32.u64 %0, t; }" : "=r"(a) : "l"(p));
    return a;
}

__device__ __forceinline__ void cp16(uint32_t dst, const void* src) {
    asm volatile("cp.async.cg.shared.global [%0], [%1], 16;" :: "r"(dst), "l"(src));
}
#define CP_COMMIT() asm volatile("cp.async.commit_group;" ::: "memory")
#define CP_WAIT(n)  asm volatile("cp.async.wait_group %0;" :: "n"(n) : "memory")

__device__ __forceinline__ void ldm4(uint32_t* r, uint32_t addr) {
    asm volatile("ldmatrix.sync.aligned.m8n8.x4.shared.b16 {%0,%1,%2,%3}, [%4];"
                 : "=r"(r[0]), "=r"(r[1]), "=r"(r[2]), "=r"(r[3]) : "r"(addr));
}

__device__ __forceinline__ void mma16816(float* d, const uint32_t* a, const uint32_t* b) {
    asm volatile("mma.sync.aligned.m16n8k16.row.col.f32.bf16.bf16.f32 "
                 "{%0,%1,%2,%3}, {%4,%5,%6,%7}, {%8,%9}, {%0,%1,%2,%3};"
                 : "+f"(d[0]), "+f"(d[1]), "+f"(d[2]), "+f"(d[3])
                 : "r"(a[0]), "r"(a[1]), "r"(a[2]), "r"(a[3]), "r"(b[0]), "r"(b[1]));
}

// ---------------------------------------------------------------------------
// split x fp32 -> bf16 hi/lo
// ---------------------------------------------------------------------------
__global__ __launch_bounds__(256)
void split_f32(const float* __restrict__ A, __nv_bfloat16* __restrict__ hi,
               __nv_bfloat16* __restrict__ lo)
{
    int i = blockIdx.x * 256 + threadIdx.x;
    float v = A[i];
    __nv_bfloat16 h = __float2bfloat16(v);
    hi[i] = h;
    lo[i] = __float2bfloat16(v - __bfloat162float(h));
}

// ---------------------------------------------------------------------------
// Transpose + split: W[(h,)k,n] fp32 -> out[(h,)n,k] bf16 hi/lo
// grid (N/32, K/32, H), block (32,8)
// ---------------------------------------------------------------------------
__global__ __launch_bounds__(256)
void tsplit(const float* __restrict__ W, __nv_bfloat16* __restrict__ hi,
            __nv_bfloat16* __restrict__ lo, int K, int N)
{
    __shared__ float t[32][33];
    const size_t hb = (size_t)blockIdx.z * (size_t)K * (size_t)N;
    const int k0 = blockIdx.y * 32, n0 = blockIdx.x * 32;
    const int x = threadIdx.x, y = threadIdx.y;
#pragma unroll
    for (int i = 0; i < 4; i++)
        t[y + 8*i][x] = W[hb + (size_t)(k0 + y + 8*i) * N + n0 + x];
    __syncthreads();
#pragma unroll
    for (int i = 0; i < 4; i++) {
        float v = t[x][y + 8*i];
        __nv_bfloat16 h = __float2bfloat16(v);
        size_t o = hb + (size_t)(n0 + y + 8*i) * K + k0 + x;
        hi[o] = h;
        lo[o] = __float2bfloat16(v - __bfloat162float(h));
    }
}

// ---------------------------------------------------------------------------
// mma.sync bf16x3 GEMM: C = A[M,K]*W[K,N], A/W fp32-split into bf16 hi/lo.
// D = Ahi.Bhi + Alo.Bhi + Ahi.Blo via 3 K-phases into one fp32 accumulator.
// Tiles: 128 x BN x 32, 8 warps in 4x2 grid (warp tile 32 x BN/2).
// A staged row-major [128][32] (+16B row pad), B = W^T staged [BN][32] (+pad).
// Both feed mma m16n8k16 row.col via plain ldmatrix (no trans).
// grid (Nfull/BN, M/128, H)
// out_kind: 0 = fp32 C[m*out_ld + col_off + n]
//           1 = fp32 per-head C[((b*16+h)*2048+s)*out_ld + col_off + n]
//           2 = bf16 hi/lo pair, row-major [M][Nfull]
// ---------------------------------------------------------------------------
template<int BN>
__global__ __launch_bounds__(256, 1)
void mma_gemm(const __nv_bfloat16* __restrict__ Ahi, const __nv_bfloat16* __restrict__ Alo,
              const __nv_bfloat16* __restrict__ Bhi, const __nv_bfloat16* __restrict__ Blo,
              float* __restrict__ Cf, __nv_bfloat16* __restrict__ Chi,
              __nv_bfloat16* __restrict__ Clo,
              int K, int Nfull, int out_kind, int col_off, int out_ld)
{
    constexpr int ROWB = 80;            // 64 B data + 16 B pad
    constexpr int ABUF = 128 * ROWB;    // 10240 B
    constexpr int BBUF = BN * ROWB;
    constexpr int BNW  = BN / 2;        // cols per warp
    constexpr int NFR  = BNW / 8;       // n8 fragments per warp

    __shared__ __align__(16) char smA[2 * ABUF];
    __shared__ __align__(16) char smB[2 * BBUF];

    const int tid  = threadIdx.x;
    const int wid  = tid >> 5;
    const int lane = tid & 31;
    const int m_blk = blockIdx.y * 128;
    const int n_blk = blockIdx.x * BN;
    const int head  = blockIdx.z;
    const int warp_m = (wid >> 1) * 32;
    const int warp_n = (wid & 1) * BNW;

    const size_t bhead = (size_t)head * (size_t)Nfull * (size_t)K;
    const __nv_bfloat16* Bh = Bhi + bhead;
    const __nv_bfloat16* Bl = Blo + bhead;

    const uint32_t sA = smem_u32(smA);
    const uint32_t sB = smem_u32(smB);

    const int KC = K >> 5;          // 32-wide chunks per phase
    const int NC = 3 * KC;

    float acc[2][NFR][4];
#pragma unroll
    for (int mi = 0; mi < 2; mi++)
#pragma unroll
        for (int ni = 0; ni < NFR; ni++)
#pragma unroll
            for (int j = 0; j < 4; j++) acc[mi][ni][j] = 0.f;

    // ---- async tile loader for chunk i into buffer buf ----
    auto load_chunk = [&](int i, int buf) {
        int ph = (i >= 2 * KC) ? 2 : (i >= KC ? 1 : 0);
        const __nv_bfloat16* Ap = (ph == 1) ? Alo : Ahi;
        const __nv_bfloat16* Bp = (ph == 2) ? Bl : Bh;
        int kt = (i - ph * KC) << 5;
        // A: 512 segments of 16B
#pragma unroll
        for (int j = 0; j < 2; j++) {
            int e = tid + j * 256;
            int r = e >> 2, s = e & 3;
            cp16(sA + buf * ABUF + r * ROWB + s * 16,
                 Ap + (size_t)(m_blk + r) * K + kt + s * 8);
        }
        // B: BN*4 segments
#pragma unroll
        for (int j = 0; j < BN / 64; j++) {
            int e = tid + j * 256;
            int r = e >> 2, s = e & 3;
            cp16(sB + buf * BBUF + r * ROWB + s * 16,
                 Bp + (size_t)(n_blk + r) * K + kt + s * 8);
        }
        CP_COMMIT();
    };

    load_chunk(0, 0);

    // fragment smem address bases (per lane)
    const uint32_t aoff = (uint32_t)((warp_m + (lane & 15)) * ROWB + ((lane >> 4) << 4));
    const uint32_t boff = (uint32_t)((warp_n + (lane & 7) + ((lane >> 4) << 3)) * ROWB +
                                     (((lane >> 3) & 1) << 4));

    for (int i = 0; i < NC; i++) {
        const int buf = i & 1;
        if (i + 1 < NC) {
            load_chunk(i + 1, buf ^ 1);
            CP_WAIT(1);
        } else {
            CP_WAIT(0);
        }
        __syncthreads();

        const uint32_t aB = sA + buf * ABUF + aoff;
        const uint32_t bB = sB + buf * BBUF + boff;
#pragma unroll
        for (int ks = 0; ks < 2; ks++) {
            uint32_t a[2][4];
            uint32_t b[NFR][2];
#pragma unroll
            for (int mi = 0; mi < 2; mi++)
                ldm4(a[mi], aB + mi * 16 * ROWB + ks * 32);
#pragma unroll
            for (int nj = 0; nj < NFR / 2; nj++) {
                uint32_t r[4];
                ldm4(r, bB + nj * 16 * ROWB + ks * 32);
                b[2*nj][0] = r[0]; b[2*nj][1] = r[1];
                b[2*nj+1][0] = r[2]; b[2*nj+1][1] = r[3];
            }
#pragma unroll
            for (int mi = 0; mi < 2; mi++)
#pragma unroll
                for (int ni = 0; ni < NFR; ni++)
                    mma16816(acc[mi][ni], a[mi], b[ni]);
        }
        __syncthreads();
    }

    // ---- epilogue: fragments -> global ----
    const int g = lane >> 2, c2 = (lane & 3) * 2;
#pragma unroll
    for (int mi = 0; mi < 2; mi++) {
#pragma unroll
        for (int ni = 0; ni < NFR; ni++) {
            int col = n_blk + warp_n + ni * 8 + c2;
#pragma unroll
            for (int hrow = 0; hrow < 2; hrow++) {
                int m = m_blk + warp_m + mi * 16 + g + hrow * 8;
                float v0 = acc[mi][ni][hrow * 2];
                float v1 = acc[mi][ni][hrow * 2 + 1];
                if (out_kind == 2) {
                    __nv_bfloat16 h0 = __float2bfloat16(v0);
                    __nv_bfloat16 h1 = __float2bfloat16(v1);
                    __nv_bfloat16 l0 = __float2bfloat16(v0 - __bfloat162float(h0));
                    __nv_bfloat16 l1 = __float2bfloat16(v1 - __bfloat162float(h1));
                    size_t o = (size_t)m * Nfull + col;
                    *(__nv_bfloat162*)(Chi + o) = __nv_bfloat162(h0, h1);
                    *(__nv_bfloat162*)(Clo + o) = __nv_bfloat162(l0, l1);
                } else if (out_kind == 1) {
                    int b = m >> 11, s = m & 2047;
                    size_t o = ((size_t)((b * Hq + head) * Sq + s)) * out_ld + col_off + col;
                    *(float2*)(Cf + o) = make_float2(v0, v1);
                } else {
                    size_t o = (size_t)m * out_ld + col_off + col;
                    *(float2*)(Cf + o) = make_float2(v0, v1);
                }
            }
        }
    }
}

// ---------------------------------------------------------------------------
// Broadcast k_r[B,S,64] into K[B,H,S,192] columns [128,192)
// ---------------------------------------------------------------------------
__global__ __launch_bounds__(256)
void bcast_k(const float* __restrict__ kr, float* __restrict__ K)
{
    int idx = blockIdx.x * 256 + threadIdx.x;
    int j = idx & 63;
    int s = (idx >> 6) & 2047;
    int h = (idx >> 17) & 15;
    int b = idx >> 21;
    K[((size_t)((b * Hq + h) * Sq + s)) * DQK + DKq + j] =
        kr[((size_t)(b * Sq + s)) * DRq + j];
}

// ---------------------------------------------------------------------------
// Causal flash attention (SIMT fp32). grid (S/64, B*H), 256 threads.
// ---------------------------------------------------------------------------
__global__ __launch_bounds__(256)
void attn_k(const float* __restrict__ Q, const float* __restrict__ Kt,
            const float* __restrict__ V, float* __restrict__ O)
{
    extern __shared__ __align__(16) float smf[];
    float* Qs = smf;                  // 192*64
    float* Ks = Qs + 192 * 64;        // 192*64
    float* Vs = Ks + 192 * 64;        // 64*128
    float* Ps = Vs + 64 * 128;        // 64*68

    const int bh = blockIdx.y;
    const int b = bh >> 4, h = bh & 15;
    const size_t qkbase = (size_t)bh * Sq * DQK;
    const size_t vbase  = (size_t)bh * Sq * DVq;
    const int s0 = blockIdx.x * 64;
    const int tid = threadIdx.x, tx = tid & 15, ty = tid >> 4;

#pragma unroll 4
    for (int e = tid; e < 64 * 192; e += 256) {
        int r = e / 192, d = e - r * 192;
        Qs[d * 64 + (r ^ ((d & 15) << 2))] = Q[qkbase + (size_t)(s0 + r) * DQK + d];
    }

    float m_i[4], l_i[4], acc[4][8];
#pragma unroll
    for (int i = 0; i < 4; i++) {
        m_i[i] = -INFINITY; l_i[i] = 0.f;
#pragma unroll
        for (int j = 0; j < 8; j++) acc[i][j] = 0.f;
    }

    const float scale = 0.07216878364870322f;   // 1/sqrt(192)
    const int jmax = blockIdx.x;

    for (int jb = 0; jb <= jmax; jb++) {
        __syncthreads();
#pragma unroll 4
        for (int e = tid; e < 64 * 192; e += 256) {
            int r = e / 192, d = e - r * 192;
            Ks[d * 64 + (r ^ ((d & 15) << 2))] =
                Kt[qkbase + (size_t)(jb * 64 + r) * DQK + d];
        }
#pragma unroll 4
        for (int e = tid; e < 64 * 128; e += 256) {
            int t = e >> 7, c = e & 127;
            Vs[e] = V[vbase + (size_t)(jb * 64 + t) * DVq + c];
        }
        __syncthreads();

        float sc[4][4];
#pragma unroll
        for (int i = 0; i < 4; i++)
#pragma unroll
            for (int j = 0; j < 4; j++) sc[i][j] = 0.f;

#pragma unroll 16
        for (int kk = 0; kk < 192; kk++) {
            const int swz = (kk & 15) << 2;
            float4 qv = *(const float4*)&Qs[kk * 64 + ((ty * 4) ^ swz)];
            float4 kv = *(const float4*)&Ks[kk * 64 + ((tx * 4) ^ swz)];
            float qa[4] = {qv.x, qv.y, qv.z, qv.w};
            float ka[4] = {kv.x, kv.y, kv.z, kv.w};
#pragma unroll
            for (int i = 0; i < 4; i++)
#pragma unroll
                for (int j = 0; j < 4; j++)
                    sc[i][j] = fmaf(qa[i], ka[j], sc[i][j]);
        }

        const bool diag = (jb == jmax);
#pragma unroll
        for (int i = 0; i < 4; i++) {
            int row = s0 + ty * 4 + i;
#pragma unroll
            for (int j = 0; j < 4; j++) {
                float v = sc[i][j] * scale;
                if (diag && (jb * 64 + tx * 4 + j) > row) v = -INFINITY;
                sc[i][j] = v;
            }
        }

#pragma unroll
        for (int i = 0; i < 4; i++) {
            float rm = fmaxf(fmaxf(sc[i][0], sc[i][1]), fmaxf(sc[i][2], sc[i][3]));
#pragma unroll
            for (int o = 8; o > 0; o >>= 1)
                rm = fmaxf(rm, __shfl_xor_sync(0xffffffffu, rm, o, 16));
            float mnew = fmaxf(m_i[i], rm);
            float alpha = __expf(m_i[i] - mnew);
            m_i[i] = mnew;
            float p0 = __expf(sc[i][0] - mnew);
            float p1 = __expf(sc[i][1] - mnew);
            float p2 = __expf(sc[i][2] - mnew);
            float p3 = __expf(sc[i][3] - mnew);
            float rs = p0 + p1 + p2 + p3;
#pragma unroll
            for (int o = 8; o > 0; o >>= 1)
                rs += __shfl_xor_sync(0xffffffffu, rs, o, 16);
            l_i[i] = l_i[i] * alpha + rs;
            *(float4*)&Ps[(ty * 4 + i) * 68 + tx * 4] = make_float4(p0, p1, p2, p3);
#pragma unroll
            for (int j = 0; j < 8; j++) acc[i][j] *= alpha;
        }
        __syncthreads();

        // PV, unrolled x4 with float4 P loads
#pragma unroll 2
        for (int t0 = 0; t0 < 64; t0 += 4) {
            float4 pr[4];
#pragma unroll
            for (int i = 0; i < 4; i++)
                pr[i] = *(const float4*)&Ps[(ty * 4 + i) * 68 + t0];
            float pm[4][4] = {
                {pr[0].x, pr[0].y, pr[0].z, pr[0].w},
                {pr[1].x, pr[1].y, pr[1].z, pr[1].w},
                {pr[2].x, pr[2].y, pr[2].z, pr[2].w},
                {pr[3].x, pr[3].y, pr[3].z, pr[3].w}};
#pragma unroll
            for (int dt = 0; dt < 4; dt++) {
                float4 v0 = *(const float4*)&Vs[(t0 + dt) * 128 + tx * 8];
                float4 v1 = *(const float4*)&Vs[(t0 + dt) * 128 + tx * 8 + 4];
#pragma unroll
                for (int i = 0; i < 4; i++) {
                    float p = pm[i][dt];
                    acc[i][0] = fmaf(p, v0.x, acc[i][0]);
                    acc[i][1] = fmaf(p, v0.y, acc[i][1]);
                    acc[i][2] = fmaf(p, v0.z, acc[i][2]);
                    acc[i][3] = fmaf(p, v0.w, acc[i][3]);
                    acc[i][4] = fmaf(p, v1.x, acc[i][4]);
                    acc[i][5] = fmaf(p, v1.y, acc[i][5]);
                    acc[i][6] = fmaf(p, v1.z, acc[i][6]);
                    acc[i][7] = fmaf(p, v1.w, acc[i][7]);
                }
            }
        }
    }

#pragma unroll
    for (int i = 0; i < 4; i++) {
        int s = s0 + ty * 4 + i;
        float inv = 1.0f / l_i[i];
        size_t o = ((size_t)(b * Sq + s)) * (size_t)(Hq * DVq) + h * DVq + tx * 8;
        float4 o0 = make_float4(acc[i][0]*inv, acc[i][1]*inv, acc[i][2]*inv, acc[i][3]*inv);
        float4 o1 = make_float4(acc[i][4]*inv, acc[i][5]*inv, acc[i][6]*inv, acc[i][7]*inv);
        *(float4*)&O[o]     = o0;
        *(float4*)&O[o + 4] = o1;
    }
}

// ---------------------------------------------------------------------------
extern "C" void kernel_launch(void* const* d_in, const int* in_sizes, int n_in,
                              void* d_out, int out_size)
{
    (void)in_sizes; (void)n_in; (void)out_size;
    const float* x    = (const float*)d_in[0];
    const float* W_c  = (const float*)d_in[1];
    const float* W_cp = (const float*)d_in[2];
    const float* W_qc = (const float*)d_in[3];
    const float* W_qr = (const float*)d_in[4];
    const float* W_kc = (const float*)d_in[5];
    const float* W_kr = (const float*)d_in[6];
    const float* W_v  = (const float*)d_in[7];
    float* out = (float*)d_out;

    char* arena;
    cudaGetSymbolAddress((void**)&arena, g_arena);
    __nv_bfloat16* xhi   = (__nv_bfloat16*)(arena + O_XHI);
    __nv_bfloat16* xlo   = (__nv_bfloat16*)(arena + O_XLO);
    __nv_bfloat16* WcTh  = (__nv_bfloat16*)(arena + O_WCTH);
    __nv_bfloat16* WcTl  = (__nv_bfloat16*)(arena + O_WCTL);
    __nv_bfloat16* WcpTh = (__nv_bfloat16*)(arena + O_WCPTH);
    __nv_bfloat16* WcpTl = (__nv_bfloat16*)(arena + O_WCPTL);
    __nv_bfloat16* WqcTh = (__nv_bfloat16*)(arena + O_WQCTH);
    __nv_bfloat16* WqcTl = (__nv_bfloat16*)(arena + O_WQCTL);
    __nv_bfloat16* WqrTh = (__nv_bfloat16*)(arena + O_WQRTH);
    __nv_bfloat16* WqrTl = (__nv_bfloat16*)(arena + O_WQRTL);
    __nv_bfloat16* WkcTh = (__nv_bfloat16*)(arena + O_WKCTH);
    __nv_bfloat16* WkcTl = (__nv_bfloat16*)(arena + O_WKCTL);
    __nv_bfloat16* WkrTh = (__nv_bfloat16*)(arena + O_WKRTH);
    __nv_bfloat16* WkrTl = (__nv_bfloat16*)(arena + O_WKRTL);
    __nv_bfloat16* WvTh  = (__nv_bfloat16*)(arena + O_WVTH);
    __nv_bfloat16* WvTl  = (__nv_bfloat16*)(arena + O_WVTL);
    __nv_bfloat16* chi   = (__nv_bfloat16*)(arena + O_CHI);
    __nv_bfloat16* clo   = (__nv_bfloat16*)(arena + O_CLO);
    __nv_bfloat16* cphi  = (__nv_bfloat16*)(arena + O_CPHI);
    __nv_bfloat16* cplo  = (__nv_bfloat16*)(arena + O_CPLO);
    float* kr = (float*)(arena + O_KR);
    float* q  = (float*)(arena + O_Q);
    float* k  = (float*)(arena + O_K);
    float* v  = (float*)(arena + O_V);

    const int ATTN_SMEM = (192*64 + 192*64 + 64*128 + 64*68) * (int)sizeof(float);
    cudaFuncSetAttribute(attn_k, cudaFuncAttributeMaxDynamicSharedMemorySize, ATTN_SMEM);

    // fp32 -> bf16 hi/lo splits (x) and transposed weight splits
    split_f32<<<32768, 256>>>(x, xhi, xlo);
    tsplit<<<dim3(16, 64, 1),  dim3(32, 8)>>>(W_c,  WcTh,  WcTl,  2048, 512);
    tsplit<<<dim3(32, 64, 1),  dim3(32, 8)>>>(W_cp, WcpTh, WcpTl, 2048, 1024);
    tsplit<<<dim3( 4, 32, 16), dim3(32, 8)>>>(W_qc, WqcTh, WqcTl, 1024, 128);
    tsplit<<<dim3( 2, 32, 16), dim3(32, 8)>>>(W_qr, WqrTh, WqrTl, 1024, 64);
    tsplit<<<dim3( 4, 16, 16), dim3(32, 8)>>>(W_kc, WkcTh, WkcTl, 512, 128);
    tsplit<<<dim3( 2, 64, 1),  dim3(32, 8)>>>(W_kr, WkrTh, WkrTl, 2048, 64);
    tsplit<<<dim3( 4, 16, 16), dim3(32, 8)>>>(W_v,  WvTh,  WvTl,  512, 128);

    // mma.sync projections (bf16x3)
    mma_gemm<128><<<dim3(4, 32, 1),  256>>>(xhi, xlo, WcTh, WcTl, nullptr, chi, clo,
                                            2048, 512, 2, 0, 0);
    mma_gemm<128><<<dim3(8, 32, 1),  256>>>(xhi, xlo, WcpTh, WcpTl, nullptr, cphi, cplo,
                                            2048, 1024, 2, 0, 0);
    mma_gemm<64> <<<dim3(1, 32, 1),  256>>>(xhi, xlo, WkrTh, WkrTl, kr, nullptr, nullptr,
                                            2048, 64, 0, 0, 64);
    mma_gemm<128><<<dim3(1, 32, 16), 256>>>(cphi, cplo, WqcTh, WqcTl, q, nullptr, nullptr,
                                            1024, 128, 1, 0, DQK);
    mma_gemm<64> <<<dim3(1, 32, 16), 256>>>(cphi, cplo, WqrTh, WqrTl, q, nullptr, nullptr,
                                            1024, 64, 1, 128, DQK);
    mma_gemm<128><<<dim3(1, 32, 16), 256>>>(chi, clo, WkcTh, WkcTl, k, nullptr, nullptr,
                                            512, 128, 1, 0, DQK);
    mma_gemm<128><<<dim3(1, 32, 16), 256>>>(chi, clo, WvTh, WvTl, v, nullptr, nullptr,
                                            512, 128, 1, 0, DVq);

    bcast_k<<<(Bq*Hq*Sq*DRq) / 256, 256>>>(kr, k);
    attn_k<<<dim3(Sq / 64, Bq * Hq), 256, ATTN_SMEM>>>(q, k, v, out);
}

// round 4
// speedup vs baseline: 3.0429x; 2.2562x over previous
#include <cuda_runtime.h>
#include <cuda_bf16.h>
#include <math.h>
#include <stdint.h>

// Problem constants
#define Bq   2
#define Sq   2048
#define DIMq 2048
#define Hq   16
#define DKq  128
#define DRq  64
#define DCq  512
#define DCPq 1024
#define DVq  128
#define DQK  192
#define Mrows (Bq*Sq)      // 4096

// ------------------------- scratch arena (bss) ------------------------------
#define O_XHI    0ULL
#define O_XLO    16777216ULL
#define O_WCTH   33554432ULL
#define O_WCTL   35651584ULL
#define O_WCPTH  37748736ULL
#define O_WCPTL  41943040ULL
#define O_WQCTH  46137344ULL
#define O_WQCTL  50331648ULL
#define O_WQRTH  54525952ULL
#define O_WQRTL  56623104ULL
#define O_WKCTH  58720256ULL
#define O_WKCTL  60817408ULL
#define O_WKRTH  62914560ULL
#define O_WKRTL  63176704ULL
#define O_WVTH   63438848ULL
#define O_WVTL   65536000ULL
#define O_CHI    67633152ULL
#define O_CLO    71827456ULL
#define O_CPHI   76021760ULL
#define O_CPLO   84410368ULL
#define O_KRH    92798976ULL
#define O_KRL    93323264ULL
#define O_QH     93847552ULL
#define O_QL     119013376ULL
#define O_KH     144179200ULL
#define O_KL     169345024ULL
#define O_VH     194510848ULL
#define O_VL     211288064ULL
#define ARENA_BYTES 228065280ULL

__device__ __align__(256) char g_arena[ARENA_BYTES];

// ------------------------- helpers ------------------------------------------
__device__ __forceinline__ uint32_t smem_u32(const void* p) {
    uint32_t a;
    asm("{ .reg .u64 t; cvta.to.shared.u64 t, %1; cvt.u32.u64 %0, t; }" : "=r"(a) : "l"(p));
    return a;
}

__device__ __forceinline__ void cp16(uint32_t dst, const void* src) {
    asm volatile("cp.async.cg.shared.global [%0], [%1], 16;" :: "r"(dst), "l"(src));
}
#define CP_COMMIT() asm volatile("cp.async.commit_group;" ::: "memory")
#define CP_WAIT(n)  asm volatile("cp.async.wait_group %0;" :: "n"(n) : "memory")

__device__ __forceinline__ void ldm4(uint32_t* r, uint32_t addr) {
    asm volatile("ldmatrix.sync.aligned.m8n8.x4.shared.b16 {%0,%1,%2,%3}, [%4];"
                 : "=r"(r[0]), "=r"(r[1]), "=r"(r[2]), "=r"(r[3]) : "r"(addr));
}
__device__ __forceinline__ void ldm4t(uint32_t* r, uint32_t addr) {
    asm volatile("ldmatrix.sync.aligned.m8n8.x4.trans.shared.b16 {%0,%1,%2,%3}, [%4];"
                 : "=r"(r[0]), "=r"(r[1]), "=r"(r[2]), "=r"(r[3]) : "r"(addr));
}

__device__ __forceinline__ void mma16816(float* d, const uint32_t* a, const uint32_t* b) {
    asm volatile("mma.sync.aligned.m16n8k16.row.col.f32.bf16.bf16.f32 "
                 "{%0,%1,%2,%3}, {%4,%5,%6,%7}, {%8,%9}, {%0,%1,%2,%3};"
                 : "+f"(d[0]), "+f"(d[1]), "+f"(d[2]), "+f"(d[3])
                 : "r"(a[0]), "r"(a[1]), "r"(a[2]), "r"(a[3]), "r"(b[0]), "r"(b[1]));
}

__device__ __forceinline__ uint32_t packbf(float x, float y) {
    __nv_bfloat162 t = __floats2bfloat162_rn(x, y);
    return *(uint32_t*)&t;
}

// ---------------------------------------------------------------------------
// split x fp32 -> bf16 hi/lo
// ---------------------------------------------------------------------------
__global__ __launch_bounds__(256)
void split_f32(const float* __restrict__ A, __nv_bfloat16* __restrict__ hi,
               __nv_bfloat16* __restrict__ lo)
{
    int i = blockIdx.x * 256 + threadIdx.x;
    float v = A[i];
    __nv_bfloat16 h = __float2bfloat16(v);
    hi[i] = h;
    lo[i] = __float2bfloat16(v - __bfloat162float(h));
}

// ---------------------------------------------------------------------------
// Transpose + split: W[(h,)k,n] fp32 -> out[(h,)n,k] bf16 hi/lo
// ---------------------------------------------------------------------------
__global__ __launch_bounds__(256)
void tsplit(const float* __restrict__ W, __nv_bfloat16* __restrict__ hi,
            __nv_bfloat16* __restrict__ lo, int K, int N)
{
    __shared__ float t[32][33];
    const size_t hb = (size_t)blockIdx.z * (size_t)K * (size_t)N;
    const int k0 = blockIdx.y * 32, n0 = blockIdx.x * 32;
    const int x = threadIdx.x, y = threadIdx.y;
#pragma unroll
    for (int i = 0; i < 4; i++)
        t[y + 8*i][x] = W[hb + (size_t)(k0 + y + 8*i) * N + n0 + x];
    __syncthreads();
#pragma unroll
    for (int i = 0; i < 4; i++) {
        float v = t[x][y + 8*i];
        __nv_bfloat16 h = __float2bfloat16(v);
        size_t o = hb + (size_t)(n0 + y + 8*i) * K + k0 + x;
        hi[o] = h;
        lo[o] = __float2bfloat16(v - __bfloat162float(h));
    }
}

// ---------------------------------------------------------------------------
// mma.sync bf16x3 GEMM (as R3), plus out_kind 3 = per-head bf16 hi/lo.
// ---------------------------------------------------------------------------
template<int BN>
__global__ __launch_bounds__(256, 1)
void mma_gemm(const __nv_bfloat16* __restrict__ Ahi, const __nv_bfloat16* __restrict__ Alo,
              const __nv_bfloat16* __restrict__ Bhi, const __nv_bfloat16* __restrict__ Blo,
              float* __restrict__ Cf, __nv_bfloat16* __restrict__ Chi,
              __nv_bfloat16* __restrict__ Clo,
              int K, int Nfull, int out_kind, int col_off, int out_ld)
{
    constexpr int ROWB = 80;
    constexpr int ABUF = 128 * ROWB;
    constexpr int BBUF = BN * ROWB;
    constexpr int BNW  = BN / 2;
    constexpr int NFR  = BNW / 8;

    __shared__ __align__(16) char smA[2 * ABUF];
    __shared__ __align__(16) char smB[2 * BBUF];

    const int tid  = threadIdx.x;
    const int wid  = tid >> 5;
    const int lane = tid & 31;
    const int m_blk = blockIdx.y * 128;
    const int n_blk = blockIdx.x * BN;
    const int head  = blockIdx.z;
    const int warp_m = (wid >> 1) * 32;
    const int warp_n = (wid & 1) * BNW;

    const size_t bhead = (size_t)head * (size_t)Nfull * (size_t)K;
    const __nv_bfloat16* Bh = Bhi + bhead;
    const __nv_bfloat16* Bl = Blo + bhead;

    const uint32_t sA = smem_u32(smA);
    const uint32_t sB = smem_u32(smB);

    const int KC = K >> 5;
    const int NC = 3 * KC;

    float acc[2][NFR][4];
#pragma unroll
    for (int mi = 0; mi < 2; mi++)
#pragma unroll
        for (int ni = 0; ni < NFR; ni++)
#pragma unroll
            for (int j = 0; j < 4; j++) acc[mi][ni][j] = 0.f;

    auto load_chunk = [&](int i, int buf) {
        int ph = (i >= 2 * KC) ? 2 : (i >= KC ? 1 : 0);
        const __nv_bfloat16* Ap = (ph == 1) ? Alo : Ahi;
        const __nv_bfloat16* Bp = (ph == 2) ? Bl : Bh;
        int kt = (i - ph * KC) << 5;
#pragma unroll
        for (int j = 0; j < 2; j++) {
            int e = tid + j * 256;
            int r = e >> 2, s = e & 3;
            cp16(sA + buf * ABUF + r * ROWB + s * 16,
                 Ap + (size_t)(m_blk + r) * K + kt + s * 8);
        }
#pragma unroll
        for (int j = 0; j < BN / 64; j++) {
            int e = tid + j * 256;
            int r = e >> 2, s = e & 3;
            cp16(sB + buf * BBUF + r * ROWB + s * 16,
                 Bp + (size_t)(n_blk + r) * K + kt + s * 8);
        }
        CP_COMMIT();
    };

    load_chunk(0, 0);

    const uint32_t aoff = (uint32_t)((warp_m + (lane & 15)) * ROWB + ((lane >> 4) << 4));
    const uint32_t boff = (uint32_t)((warp_n + (lane & 7) + ((lane >> 4) << 3)) * ROWB +
                                     (((lane >> 3) & 1) << 4));

    for (int i = 0; i < NC; i++) {
        const int buf = i & 1;
        if (i + 1 < NC) {
            load_chunk(i + 1, buf ^ 1);
            CP_WAIT(1);
        } else {
            CP_WAIT(0);
        }
        __syncthreads();

        const uint32_t aB = sA + buf * ABUF + aoff;
        const uint32_t bB = sB + buf * BBUF + boff;
#pragma unroll
        for (int ks = 0; ks < 2; ks++) {
            uint32_t a[2][4];
            uint32_t b[NFR][2];
#pragma unroll
            for (int mi = 0; mi < 2; mi++)
                ldm4(a[mi], aB + mi * 16 * ROWB + ks * 32);
#pragma unroll
            for (int nj = 0; nj < NFR / 2; nj++) {
                uint32_t r[4];
                ldm4(r, bB + nj * 16 * ROWB + ks * 32);
                b[2*nj][0] = r[0]; b[2*nj][1] = r[1];
                b[2*nj+1][0] = r[2]; b[2*nj+1][1] = r[3];
            }
#pragma unroll
            for (int mi = 0; mi < 2; mi++)
#pragma unroll
                for (int ni = 0; ni < NFR; ni++)
                    mma16816(acc[mi][ni], a[mi], b[ni]);
        }
        __syncthreads();
    }

    const int g = lane >> 2, c2 = (lane & 3) * 2;
#pragma unroll
    for (int mi = 0; mi < 2; mi++) {
#pragma unroll
        for (int ni = 0; ni < NFR; ni++) {
            int col = n_blk + warp_n + ni * 8 + c2;
#pragma unroll
            for (int hrow = 0; hrow < 2; hrow++) {
                int m = m_blk + warp_m + mi * 16 + g + hrow * 8;
                float v0 = acc[mi][ni][hrow * 2];
                float v1 = acc[mi][ni][hrow * 2 + 1];
                if (out_kind == 2) {
                    __nv_bfloat16 h0 = __float2bfloat16(v0);
                    __nv_bfloat16 h1 = __float2bfloat16(v1);
                    __nv_bfloat16 l0 = __float2bfloat16(v0 - __bfloat162float(h0));
                    __nv_bfloat16 l1 = __float2bfloat16(v1 - __bfloat162float(h1));
                    size_t o = (size_t)m * Nfull + col;
                    *(__nv_bfloat162*)(Chi + o) = __nv_bfloat162(h0, h1);
                    *(__nv_bfloat162*)(Clo + o) = __nv_bfloat162(l0, l1);
                } else if (out_kind == 3) {
                    int b = m >> 11, s = m & 2047;
                    size_t o = ((size_t)((b * Hq + head) * Sq + s)) * out_ld + col_off + col;
                    __nv_bfloat16 h0 = __float2bfloat16(v0);
                    __nv_bfloat16 h1 = __float2bfloat16(v1);
                    __nv_bfloat16 l0 = __float2bfloat16(v0 - __bfloat162float(h0));
                    __nv_bfloat16 l1 = __float2bfloat16(v1 - __bfloat162float(h1));
                    *(__nv_bfloat162*)(Chi + o) = __nv_bfloat162(h0, h1);
                    *(__nv_bfloat162*)(Clo + o) = __nv_bfloat162(l0, l1);
                } else if (out_kind == 1) {
                    int b = m >> 11, s = m & 2047;
                    size_t o = ((size_t)((b * Hq + head) * Sq + s)) * out_ld + col_off + col;
                    *(float2*)(Cf + o) = make_float2(v0, v1);
                } else {
                    size_t o = (size_t)m * out_ld + col_off + col;
                    *(float2*)(Cf + o) = make_float2(v0, v1);
                }
            }
        }
    }
}

// ---------------------------------------------------------------------------
// Broadcast kr bf16 hi/lo [B,S,64] into k hi/lo [B,H,S,192] cols [128,192)
// (operates on uint32 = bf16 pairs)
// ---------------------------------------------------------------------------
__global__ __launch_bounds__(256)
void bcast_k(const uint32_t* __restrict__ krh, const uint32_t* __restrict__ krl,
             uint32_t* __restrict__ kh, uint32_t* __restrict__ kl)
{
    int idx = blockIdx.x * 256 + threadIdx.x;   // B*H*S*32
    int j = idx & 31;
    int s = (idx >> 5) & 2047;
    int h = (idx >> 16) & 15;
    int b = idx >> 20;
    uint32_t src = (uint32_t)((b * Sq + s) * 32 + j);
    size_t dst = ((size_t)((b * Hq + h) * Sq + s)) * 96 + 64 + j;
    kh[dst] = krh[src];
    kl[dst] = krl[src];
}

// ---------------------------------------------------------------------------
// Causal flash attention on mma.sync bf16x3.
// grid (S/128, B*H), 256 threads (8 warps x m16 rows).
// Q resident in smem (hi/lo), K/V tiles (64 keys) loaded per block.
// ---------------------------------------------------------------------------
#define QSTRB 416   // 192 bf16 -> 208 elems row pad (bytes)
#define VSTRB 272   // 128 bf16 -> 136 elems row pad (bytes)
#define SM_QH 0
#define SM_QL 53248
#define SM_KH 106496
#define SM_KL 133120
#define SM_VH 159744
#define SM_VL 177152
#define ATTN_SMEM 194560

__global__ __launch_bounds__(256, 1)
void attn_mma(const __nv_bfloat16* __restrict__ qh_, const __nv_bfloat16* __restrict__ ql_,
              const __nv_bfloat16* __restrict__ kh_, const __nv_bfloat16* __restrict__ kl_,
              const __nv_bfloat16* __restrict__ vh_, const __nv_bfloat16* __restrict__ vl_,
              float* __restrict__ O)
{
    extern __shared__ __align__(16) char sm[];
    const uint32_t sb = smem_u32(sm);

    const int bh = blockIdx.y;
    const int b = bh >> 4, h = bh & 15;
    const int s0 = ((int)gridDim.x - 1 - (int)blockIdx.x) * 128;
    const int tid = threadIdx.x, wid = tid >> 5, lane = tid & 31;
    const int warp_m = wid * 16;
    const int g = lane >> 2, c2 = (lane & 3) * 2;

    const size_t qkb = (size_t)bh * Sq * DQK;
    const size_t vb  = (size_t)bh * Sq * DVq;

    // ---- Q tile (hi/lo) -> smem, resident for the whole kernel ----
    {
        const __nv_bfloat16* sh = qh_ + qkb + (size_t)s0 * DQK;
        const __nv_bfloat16* sl = ql_ + qkb + (size_t)s0 * DQK;
#pragma unroll
        for (int j = 0; j < 12; j++) {
            int e = tid + j * 256;            // 0..3071
            int r = e / 24, s = e - r * 24;
            cp16(sb + SM_QH + r * QSTRB + s * 16, sh + r * 192 + s * 8);
            cp16(sb + SM_QL + r * QSTRB + s * 16, sl + r * 192 + s * 8);
        }
        CP_COMMIT();
    }

    float accO[16][4];
#pragma unroll
    for (int nf = 0; nf < 16; nf++)
#pragma unroll
        for (int j = 0; j < 4; j++) accO[nf][j] = 0.f;
    float m0 = -INFINITY, m1 = -INFINITY, l0 = 0.f, l1 = 0.f;

    const float scale = 0.07216878364870322f;   // 1/sqrt(192)
    const int jmax = (s0 >> 6) + 1;

    const uint32_t a_off = (uint32_t)((warp_m + (lane & 15)) * QSTRB + ((lane >> 4) << 4));
    const uint32_t b_off = (uint32_t)(((lane & 7) + ((lane >> 4) << 3)) * QSTRB +
                                      (((lane >> 3) & 1) << 4));
    const uint32_t v_off = (uint32_t)((lane & 15) * VSTRB + ((lane >> 4) << 4));

    const int row0 = s0 + warp_m + g;
    const int row1 = row0 + 8;

    for (int jb = 0; jb <= jmax; jb++) {
        // ---- load K/V tile ----
        {
            const __nv_bfloat16* skh = kh_ + qkb + (size_t)(jb * 64) * DQK;
            const __nv_bfloat16* skl = kl_ + qkb + (size_t)(jb * 64) * DQK;
            const __nv_bfloat16* svh = vh_ + vb + (size_t)(jb * 64) * DVq;
            const __nv_bfloat16* svl = vl_ + vb + (size_t)(jb * 64) * DVq;
#pragma unroll
            for (int j = 0; j < 6; j++) {
                int e = tid + j * 256;        // 0..1535
                int r = e / 24, s = e - r * 24;
                cp16(sb + SM_KH + r * QSTRB + s * 16, skh + r * 192 + s * 8);
                cp16(sb + SM_KL + r * QSTRB + s * 16, skl + r * 192 + s * 8);
            }
#pragma unroll
            for (int j = 0; j < 4; j++) {
                int e = tid + j * 256;        // 0..1023
                int r = e >> 4, s = e & 15;
                cp16(sb + SM_VH + r * VSTRB + s * 16, svh + r * 128 + s * 8);
                cp16(sb + SM_VL + r * VSTRB + s * 16, svl + r * 128 + s * 8);
            }
            CP_COMMIT();
            CP_WAIT(0);
            __syncthreads();
        }

        // ---- S = Q K^T (bf16x3) ----
        float S[8][4];
#pragma unroll
        for (int nf = 0; nf < 8; nf++)
#pragma unroll
            for (int j = 0; j < 4; j++) S[nf][j] = 0.f;

#pragma unroll
        for (int ks = 0; ks < 12; ks++) {
            uint32_t ah[4], al[4];
            ldm4(ah, sb + SM_QH + a_off + ks * 32);
            ldm4(al, sb + SM_QL + a_off + ks * 32);
#pragma unroll
            for (int p = 0; p < 4; p++) {
                uint32_t bv[4];
                ldm4(bv, sb + SM_KH + b_off + p * 16 * QSTRB + ks * 32);
                mma16816(S[2*p],   ah, bv);
                mma16816(S[2*p+1], ah, bv + 2);
                mma16816(S[2*p],   al, bv);
                mma16816(S[2*p+1], al, bv + 2);
            }
#pragma unroll
            for (int p = 0; p < 4; p++) {
                uint32_t bv[4];
                ldm4(bv, sb + SM_KL + b_off + p * 16 * QSTRB + ks * 32);
                mma16816(S[2*p],   ah, bv);
                mma16816(S[2*p+1], ah, bv + 2);
            }
        }

        // ---- scale + causal mask ----
        const bool domask = ((jb << 6) + 63) > row0;
#pragma unroll
        for (int nf = 0; nf < 8; nf++) {
#pragma unroll
            for (int j = 0; j < 4; j++) S[nf][j] *= scale;
            if (domask) {
                int key0 = (jb << 6) + nf * 8 + c2;
                if (key0     > row0) S[nf][0] = -INFINITY;
                if (key0 + 1 > row0) S[nf][1] = -INFINITY;
                if (key0     > row1) S[nf][2] = -INFINITY;
                if (key0 + 1 > row1) S[nf][3] = -INFINITY;
            }
        }

        // ---- online softmax (rows g and g+8; quad-local reductions) ----
        float rm0 = -INFINITY, rm1 = -INFINITY;
#pragma unroll
        for (int nf = 0; nf < 8; nf++) {
            rm0 = fmaxf(rm0, fmaxf(S[nf][0], S[nf][1]));
            rm1 = fmaxf(rm1, fmaxf(S[nf][2], S[nf][3]));
        }
        rm0 = fmaxf(rm0, __shfl_xor_sync(0xffffffffu, rm0, 1));
        rm0 = fmaxf(rm0, __shfl_xor_sync(0xffffffffu, rm0, 2));
        rm1 = fmaxf(rm1, __shfl_xor_sync(0xffffffffu, rm1, 1));
        rm1 = fmaxf(rm1, __shfl_xor_sync(0xffffffffu, rm1, 2));

        float mn0 = fmaxf(m0, rm0), mn1 = fmaxf(m1, rm1);
        float al0 = __expf(m0 - mn0), al1 = __expf(m1 - mn1);
        m0 = mn0; m1 = mn1;

        float rs0 = 0.f, rs1 = 0.f;
#pragma unroll
        for (int nf = 0; nf < 8; nf++) {
            S[nf][0] = __expf(S[nf][0] - mn0);
            S[nf][1] = __expf(S[nf][1] - mn0);
            S[nf][2] = __expf(S[nf][2] - mn1);
            S[nf][3] = __expf(S[nf][3] - mn1);
            rs0 += S[nf][0] + S[nf][1];
            rs1 += S[nf][2] + S[nf][3];
        }
        rs0 += __shfl_xor_sync(0xffffffffu, rs0, 1);
        rs0 += __shfl_xor_sync(0xffffffffu, rs0, 2);
        rs1 += __shfl_xor_sync(0xffffffffu, rs1, 1);
        rs1 += __shfl_xor_sync(0xffffffffu, rs1, 2);
        l0 = l0 * al0 + rs0;
        l1 = l1 * al1 + rs1;

        // ---- rescale O acc ----
#pragma unroll
        for (int nf = 0; nf < 16; nf++) {
            accO[nf][0] *= al0; accO[nf][1] *= al0;
            accO[nf][2] *= al1; accO[nf][3] *= al1;
        }

        // ---- pack P fragments (hi/lo) ----
        uint32_t ph[4][4], pl[4][4];
#pragma unroll
        for (int t = 0; t < 4; t++) {
            float v00 = S[2*t][0],   v01 = S[2*t][1];
            float v10 = S[2*t][2],   v11 = S[2*t][3];
            float v20 = S[2*t+1][0], v21 = S[2*t+1][1];
            float v30 = S[2*t+1][2], v31 = S[2*t+1][3];
            ph[t][0] = packbf(v00, v01);
            ph[t][1] = packbf(v10, v11);
            ph[t][2] = packbf(v20, v21);
            ph[t][3] = packbf(v30, v31);
            __nv_bfloat162 h0 = *(__nv_bfloat162*)&ph[t][0];
            __nv_bfloat162 h1 = *(__nv_bfloat162*)&ph[t][1];
            __nv_bfloat162 h2 = *(__nv_bfloat162*)&ph[t][2];
            __nv_bfloat162 h3 = *(__nv_bfloat162*)&ph[t][3];
            pl[t][0] = packbf(v00 - __low2float(h0), v01 - __high2float(h0));
            pl[t][1] = packbf(v10 - __low2float(h1), v11 - __high2float(h1));
            pl[t][2] = packbf(v20 - __low2float(h2), v21 - __high2float(h2));
            pl[t][3] = packbf(v30 - __low2float(h3), v31 - __high2float(h3));
        }

        // ---- O += P V (bf16x3); V^T operand via trans ldmatrix ----
#pragma unroll
        for (int t = 0; t < 4; t++) {
#pragma unroll
            for (int p = 0; p < 8; p++) {
                uint32_t bv[4];
                ldm4t(bv, sb + SM_VH + v_off + t * 16 * VSTRB + p * 32);
                mma16816(accO[2*p],   ph[t], bv);
                mma16816(accO[2*p+1], ph[t], bv + 2);
                mma16816(accO[2*p],   pl[t], bv);
                mma16816(accO[2*p+1], pl[t], bv + 2);
                ldm4t(bv, sb + SM_VL + v_off + t * 16 * VSTRB + p * 32);
                mma16816(accO[2*p],   ph[t], bv);
                mma16816(accO[2*p+1], ph[t], bv + 2);
            }
        }
        __syncthreads();   // all warps done with K/V before next load
    }

    // ---- epilogue ----
    float inv0 = 1.0f / l0, inv1 = 1.0f / l1;
#pragma unroll
    for (int nf = 0; nf < 16; nf++) {
        int col = h * DVq + nf * 8 + c2;
        size_t o0 = ((size_t)(b * Sq + row0)) * (size_t)(Hq * DVq) + col;
        size_t o1 = ((size_t)(b * Sq + row1)) * (size_t)(Hq * DVq) + col;
        *(float2*)(O + o0) = make_float2(accO[nf][0] * inv0, accO[nf][1] * inv0);
        *(float2*)(O + o1) = make_float2(accO[nf][2] * inv1, accO[nf][3] * inv1);
    }
}

// ---------------------------------------------------------------------------
extern "C" void kernel_launch(void* const* d_in, const int* in_sizes, int n_in,
                              void* d_out, int out_size)
{
    (void)in_sizes; (void)n_in; (void)out_size;
    const float* x    = (const float*)d_in[0];
    const float* W_c  = (const float*)d_in[1];
    const float* W_cp = (const float*)d_in[2];
    const float* W_qc = (const float*)d_in[3];
    const float* W_qr = (const float*)d_in[4];
    const float* W_kc = (const float*)d_in[5];
    const float* W_kr = (const float*)d_in[6];
    const float* W_v  = (const float*)d_in[7];
    float* out = (float*)d_out;

    char* arena;
    cudaGetSymbolAddress((void**)&arena, g_arena);
    __nv_bfloat16* xhi   = (__nv_bfloat16*)(arena + O_XHI);
    __nv_bfloat16* xlo   = (__nv_bfloat16*)(arena + O_XLO);
    __nv_bfloat16* WcTh  = (__nv_bfloat16*)(arena + O_WCTH);
    __nv_bfloat16* WcTl  = (__nv_bfloat16*)(arena + O_WCTL);
    __nv_bfloat16* WcpTh = (__nv_bfloat16*)(arena + O_WCPTH);
    __nv_bfloat16* WcpTl = (__nv_bfloat16*)(arena + O_WCPTL);
    __nv_bfloat16* WqcTh = (__nv_bfloat16*)(arena + O_WQCTH);
    __nv_bfloat16* WqcTl = (__nv_bfloat16*)(arena + O_WQCTL);
    __nv_bfloat16* WqrTh = (__nv_bfloat16*)(arena + O_WQRTH);
    __nv_bfloat16* WqrTl = (__nv_bfloat16*)(arena + O_WQRTL);
    __nv_bfloat16* WkcTh = (__nv_bfloat16*)(arena + O_WKCTH);
    __nv_bfloat16* WkcTl = (__nv_bfloat16*)(arena + O_WKCTL);
    __nv_bfloat16* WkrTh = (__nv_bfloat16*)(arena + O_WKRTH);
    __nv_bfloat16* WkrTl = (__nv_bfloat16*)(arena + O_WKRTL);
    __nv_bfloat16* WvTh  = (__nv_bfloat16*)(arena + O_WVTH);
    __nv_bfloat16* WvTl  = (__nv_bfloat16*)(arena + O_WVTL);
    __nv_bfloat16* chi   = (__nv_bfloat16*)(arena + O_CHI);
    __nv_bfloat16* clo   = (__nv_bfloat16*)(arena + O_CLO);
    __nv_bfloat16* cphi  = (__nv_bfloat16*)(arena + O_CPHI);
    __nv_bfloat16* cplo  = (__nv_bfloat16*)(arena + O_CPLO);
    __nv_bfloat16* krh   = (__nv_bfloat16*)(arena + O_KRH);
    __nv_bfloat16* krl   = (__nv_bfloat16*)(arena + O_KRL);
    __nv_bfloat16* qh    = (__nv_bfloat16*)(arena + O_QH);
    __nv_bfloat16* ql    = (__nv_bfloat16*)(arena + O_QL);
    __nv_bfloat16* kh    = (__nv_bfloat16*)(arena + O_KH);
    __nv_bfloat16* kl    = (__nv_bfloat16*)(arena + O_KL);
    __nv_bfloat16* vh    = (__nv_bfloat16*)(arena + O_VH);
    __nv_bfloat16* vl    = (__nv_bfloat16*)(arena + O_VL);

    cudaFuncSetAttribute(attn_mma, cudaFuncAttributeMaxDynamicSharedMemorySize, ATTN_SMEM);

    // fp32 -> bf16 hi/lo splits
    split_f32<<<32768, 256>>>(x, xhi, xlo);
    tsplit<<<dim3(16, 64, 1),  dim3(32, 8)>>>(W_c,  WcTh,  WcTl,  2048, 512);
    tsplit<<<dim3(32, 64, 1),  dim3(32, 8)>>>(W_cp, WcpTh, WcpTl, 2048, 1024);
    tsplit<<<dim3( 4, 32, 16), dim3(32, 8)>>>(W_qc, WqcTh, WqcTl, 1024, 128);
    tsplit<<<dim3( 2, 32, 16), dim3(32, 8)>>>(W_qr, WqrTh, WqrTl, 1024, 64);
    tsplit<<<dim3( 4, 16, 16), dim3(32, 8)>>>(W_kc, WkcTh, WkcTl, 512, 128);
    tsplit<<<dim3( 2, 64, 1),  dim3(32, 8)>>>(W_kr, WkrTh, WkrTl, 2048, 64);
    tsplit<<<dim3( 4, 16, 16), dim3(32, 8)>>>(W_v,  WvTh,  WvTl,  512, 128);

    // projections (bf16x3 mma.sync)
    mma_gemm<128><<<dim3(4, 32, 1),  256>>>(xhi, xlo, WcTh, WcTl, nullptr, chi, clo,
                                            2048, 512, 2, 0, 0);
    mma_gemm<128><<<dim3(8, 32, 1),  256>>>(xhi, xlo, WcpTh, WcpTl, nullptr, cphi, cplo,
                                            2048, 1024, 2, 0, 0);
    mma_gemm<64> <<<dim3(1, 32, 1),  256>>>(xhi, xlo, WkrTh, WkrTl, nullptr, krh, krl,
                                            2048, 64, 2, 0, 0);
    mma_gemm<128><<<dim3(1, 32, 16), 256>>>(cphi, cplo, WqcTh, WqcTl, nullptr, qh, ql,
                                            1024, 128, 3, 0, DQK);
    mma_gemm<64> <<<dim3(1, 32, 16), 256>>>(cphi, cplo, WqrTh, WqrTl, nullptr, qh, ql,
                                            1024, 64, 3, 128, DQK);
    mma_gemm<128><<<dim3(1, 32, 16), 256>>>(chi, clo, WkcTh, WkcTl, nullptr, kh, kl,
                                            512, 128, 3, 0, DQK);
    mma_gemm<128><<<dim3(1, 32, 16), 256>>>(chi, clo, WvTh, WvTl, nullptr, vh, vl,
                                            512, 128, 3, 0, DVq);

    bcast_k<<<(Bq*Hq*Sq*32) / 256, 256>>>((const uint32_t*)krh, (const uint32_t*)krl,
                                          (uint32_t*)kh, (uint32_t*)kl);
    attn_mma<<<dim3(Sq / 128, Bq * Hq), 256, ATTN_SMEM>>>(qh, ql, kh, kl, vh, vl, out);
}

// round 5
// speedup vs baseline: 3.8265x; 1.2576x over previous
#include <cuda_runtime.h>
#include <cuda_bf16.h>
#include <math.h>
#include <stdint.h>

// Problem constants
#define Bq   2
#define Sq   2048
#define DIMq 2048
#define Hq   16
#define DKq  128
#define DRq  64
#define DCq  512
#define DCPq 1024
#define DVq  128
#define DQK  192
#define Mrows (Bq*Sq)      // 4096

// ------------------------- scratch arena (bss) ------------------------------
#define O_XHI    0ULL
#define O_XLO    16777216ULL
#define O_WCTH   33554432ULL
#define O_WCTL   35651584ULL
#define O_WCPTH  37748736ULL
#define O_WCPTL  41943040ULL
#define O_WQCTH  46137344ULL
#define O_WQCTL  50331648ULL
#define O_WQRTH  54525952ULL
#define O_WQRTL  56623104ULL
#define O_WKCTH  58720256ULL
#define O_WKCTL  60817408ULL
#define O_WKRTH  62914560ULL
#define O_WKRTL  63176704ULL
#define O_WVTH   63438848ULL
#define O_WVTL   65536000ULL
#define O_CHI    67633152ULL
#define O_CLO    71827456ULL
#define O_CPHI   76021760ULL
#define O_CPLO   84410368ULL
#define O_KRH    92798976ULL
#define O_KRL    93323264ULL
#define O_QH     93847552ULL
#define O_QL     119013376ULL
#define O_KH     144179200ULL
#define O_KL     169345024ULL
#define O_VH     194510848ULL
#define O_VL     211288064ULL
#define ARENA_BYTES 228065280ULL

__device__ __align__(256) char g_arena[ARENA_BYTES];

// ------------------------- helpers ------------------------------------------
__device__ __forceinline__ uint32_t smem_u32(const void* p) {
    uint32_t a;
    asm("{ .reg .u64 t; cvta.to.shared.u64 t, %1; cvt.u32.u64 %0, t; }" : "=r"(a) : "l"(p));
    return a;
}

__device__ __forceinline__ void cp16(uint32_t dst, const void* src) {
    asm volatile("cp.async.cg.shared.global [%0], [%1], 16;" :: "r"(dst), "l"(src));
}
#define CP_COMMIT() asm volatile("cp.async.commit_group;" ::: "memory")
#define CP_WAIT(n)  asm volatile("cp.async.wait_group %0;" :: "n"(n) : "memory")

__device__ __forceinline__ void ldm4(uint32_t* r, uint32_t addr) {
    asm volatile("ldmatrix.sync.aligned.m8n8.x4.shared.b16 {%0,%1,%2,%3}, [%4];"
                 : "=r"(r[0]), "=r"(r[1]), "=r"(r[2]), "=r"(r[3]) : "r"(addr));
}
__device__ __forceinline__ void ldm4t(uint32_t* r, uint32_t addr) {
    asm volatile("ldmatrix.sync.aligned.m8n8.x4.trans.shared.b16 {%0,%1,%2,%3}, [%4];"
                 : "=r"(r[0]), "=r"(r[1]), "=r"(r[2]), "=r"(r[3]) : "r"(addr));
}

__device__ __forceinline__ void mma16816(float* d, const uint32_t* a, const uint32_t* b) {
    asm volatile("mma.sync.aligned.m16n8k16.row.col.f32.bf16.bf16.f32 "
                 "{%0,%1,%2,%3}, {%4,%5,%6,%7}, {%8,%9}, {%0,%1,%2,%3};"
                 : "+f"(d[0]), "+f"(d[1]), "+f"(d[2]), "+f"(d[3])
                 : "r"(a[0]), "r"(a[1]), "r"(a[2]), "r"(a[3]), "r"(b[0]), "r"(b[1]));
}

__device__ __forceinline__ uint32_t packbf(float x, float y) {
    __nv_bfloat162 t = __floats2bfloat162_rn(x, y);
    return *(uint32_t*)&t;
}

// ---------------------------------------------------------------------------
// split x fp32 -> bf16 hi/lo
// ---------------------------------------------------------------------------
__global__ __launch_bounds__(256)
void split_f32(const float* __restrict__ A, __nv_bfloat16* __restrict__ hi,
               __nv_bfloat16* __restrict__ lo)
{
    int i = blockIdx.x * 256 + threadIdx.x;
    float v = A[i];
    __nv_bfloat16 h = __float2bfloat16(v);
    hi[i] = h;
    lo[i] = __float2bfloat16(v - __bfloat162float(h));
}

// ---------------------------------------------------------------------------
// Transpose + split: W[(h,)k,n] fp32 -> out[(h,)n,k] bf16 hi/lo
// ---------------------------------------------------------------------------
__global__ __launch_bounds__(256)
void tsplit(const float* __restrict__ W, __nv_bfloat16* __restrict__ hi,
            __nv_bfloat16* __restrict__ lo, int K, int N)
{
    __shared__ float t[32][33];
    const size_t hb = (size_t)blockIdx.z * (size_t)K * (size_t)N;
    const int k0 = blockIdx.y * 32, n0 = blockIdx.x * 32;
    const int x = threadIdx.x, y = threadIdx.y;
#pragma unroll
    for (int i = 0; i < 4; i++)
        t[y + 8*i][x] = W[hb + (size_t)(k0 + y + 8*i) * N + n0 + x];
    __syncthreads();
#pragma unroll
    for (int i = 0; i < 4; i++) {
        float v = t[x][y + 8*i];
        __nv_bfloat16 h = __float2bfloat16(v);
        size_t o = hb + (size_t)(n0 + y + 8*i) * K + k0 + x;
        hi[o] = h;
        lo[o] = __float2bfloat16(v - __bfloat162float(h));
    }
}

// ---------------------------------------------------------------------------
// mma.sync bf16x3 GEMM, k=64 chunks, ROWB=144 (conflict-free), dynamic smem.
// out_kind: 0 fp32 flat, 1 fp32 per-head, 2 bf16 hi/lo flat, 3 bf16 hi/lo per-head
// ---------------------------------------------------------------------------
template<int BN>
__global__ __launch_bounds__(256, 1)
void mma_gemm(const __nv_bfloat16* __restrict__ Ahi, const __nv_bfloat16* __restrict__ Alo,
              const __nv_bfloat16* __restrict__ Bhi, const __nv_bfloat16* __restrict__ Blo,
              float* __restrict__ Cf, __nv_bfloat16* __restrict__ Chi,
              __nv_bfloat16* __restrict__ Clo,
              int K, int Nfull, int out_kind, int col_off, int out_ld)
{
    constexpr int ROWB = 144;           // 128 B data + 16 B pad
    constexpr int ABUF = 128 * ROWB;    // 18432 B
    constexpr int BBUF = BN * ROWB;
    constexpr int BUFSZ = ABUF + BBUF;
    constexpr int BNW  = BN / 2;
    constexpr int NFR  = BNW / 8;

    extern __shared__ __align__(16) char smg[];

    const int tid  = threadIdx.x;
    const int wid  = tid >> 5;
    const int lane = tid & 31;
    const int m_blk = blockIdx.y * 128;
    const int n_blk = blockIdx.x * BN;
    const int head  = blockIdx.z;
    const int warp_m = (wid >> 1) * 32;
    const int warp_n = (wid & 1) * BNW;

    const size_t bhead = (size_t)head * (size_t)Nfull * (size_t)K;
    const __nv_bfloat16* Bh = Bhi + bhead;
    const __nv_bfloat16* Bl = Blo + bhead;

    const uint32_t sb = smem_u32(smg);

    const int KC = K >> 6;          // 64-wide chunks per phase
    const int NC = 3 * KC;

    float acc[2][NFR][4];
#pragma unroll
    for (int mi = 0; mi < 2; mi++)
#pragma unroll
        for (int ni = 0; ni < NFR; ni++)
#pragma unroll
            for (int j = 0; j < 4; j++) acc[mi][ni][j] = 0.f;

    auto load_chunk = [&](int i, int buf) {
        int ph = (i >= 2 * KC) ? 2 : (i >= KC ? 1 : 0);
        const __nv_bfloat16* Ap = (ph == 1) ? Alo : Ahi;
        const __nv_bfloat16* Bp = (ph == 2) ? Bl : Bh;
        int kt = (i - ph * KC) << 6;
        const uint32_t db = sb + buf * BUFSZ;
#pragma unroll
        for (int j = 0; j < 4; j++) {
            int e = tid + j * 256;          // 0..1023
            int r = e >> 3, s = e & 7;
            cp16(db + r * ROWB + s * 16, Ap + (size_t)(m_blk + r) * K + kt + s * 8);
        }
#pragma unroll
        for (int j = 0; j < BN / 32; j++) {
            int e = tid + j * 256;
            int r = e >> 3, s = e & 7;
            cp16(db + ABUF + r * ROWB + s * 16, Bp + (size_t)(n_blk + r) * K + kt + s * 8);
        }
        CP_COMMIT();
    };

    load_chunk(0, 0);

    const uint32_t aoff = (uint32_t)((warp_m + (lane & 15)) * ROWB + ((lane >> 4) << 4));
    const uint32_t boff = (uint32_t)((warp_n + (lane & 7) + ((lane >> 4) << 3)) * ROWB +
                                     (((lane >> 3) & 1) << 4));

    for (int i = 0; i < NC; i++) {
        const int buf = i & 1;
        if (i + 1 < NC) {
            load_chunk(i + 1, buf ^ 1);
            CP_WAIT(1);
        } else {
            CP_WAIT(0);
        }
        __syncthreads();

        const uint32_t aB = sb + buf * BUFSZ + aoff;
        const uint32_t bB = sb + buf * BUFSZ + ABUF + boff;
#pragma unroll
        for (int ks = 0; ks < 4; ks++) {
            uint32_t a[2][4];
            uint32_t b[NFR][2];
#pragma unroll
            for (int mi = 0; mi < 2; mi++)
                ldm4(a[mi], aB + mi * 16 * ROWB + ks * 32);
#pragma unroll
            for (int nj = 0; nj < NFR / 2; nj++) {
                uint32_t r[4];
                ldm4(r, bB + nj * 16 * ROWB + ks * 32);
                b[2*nj][0] = r[0]; b[2*nj][1] = r[1];
                b[2*nj+1][0] = r[2]; b[2*nj+1][1] = r[3];
            }
#pragma unroll
            for (int mi = 0; mi < 2; mi++)
#pragma unroll
                for (int ni = 0; ni < NFR; ni++)
                    mma16816(acc[mi][ni], a[mi], b[ni]);
        }
        __syncthreads();
    }

    const int g = lane >> 2, c2 = (lane & 3) * 2;
#pragma unroll
    for (int mi = 0; mi < 2; mi++) {
#pragma unroll
        for (int ni = 0; ni < NFR; ni++) {
            int col = n_blk + warp_n + ni * 8 + c2;
#pragma unroll
            for (int hrow = 0; hrow < 2; hrow++) {
                int m = m_blk + warp_m + mi * 16 + g + hrow * 8;
                float v0 = acc[mi][ni][hrow * 2];
                float v1 = acc[mi][ni][hrow * 2 + 1];
                if (out_kind == 2) {
                    __nv_bfloat16 h0 = __float2bfloat16(v0);
                    __nv_bfloat16 h1 = __float2bfloat16(v1);
                    __nv_bfloat16 l0 = __float2bfloat16(v0 - __bfloat162float(h0));
                    __nv_bfloat16 l1 = __float2bfloat16(v1 - __bfloat162float(h1));
                    size_t o = (size_t)m * Nfull + col;
                    *(__nv_bfloat162*)(Chi + o) = __nv_bfloat162(h0, h1);
                    *(__nv_bfloat162*)(Clo + o) = __nv_bfloat162(l0, l1);
                } else if (out_kind == 3) {
                    int b = m >> 11, s = m & 2047;
                    size_t o = ((size_t)((b * Hq + head) * Sq + s)) * out_ld + col_off + col;
                    __nv_bfloat16 h0 = __float2bfloat16(v0);
                    __nv_bfloat16 h1 = __float2bfloat16(v1);
                    __nv_bfloat16 l0 = __float2bfloat16(v0 - __bfloat162float(h0));
                    __nv_bfloat16 l1 = __float2bfloat16(v1 - __bfloat162float(h1));
                    *(__nv_bfloat162*)(Chi + o) = __nv_bfloat162(h0, h1);
                    *(__nv_bfloat162*)(Clo + o) = __nv_bfloat162(l0, l1);
                } else if (out_kind == 1) {
                    int b = m >> 11, s = m & 2047;
                    size_t o = ((size_t)((b * Hq + head) * Sq + s)) * out_ld + col_off + col;
                    *(float2*)(Cf + o) = make_float2(v0, v1);
                } else {
                    size_t o = (size_t)m * out_ld + col_off + col;
                    *(float2*)(Cf + o) = make_float2(v0, v1);
                }
            }
        }
    }
}

// ---------------------------------------------------------------------------
// Broadcast kr bf16 hi/lo [B,S,64] into k hi/lo [B,H,S,192] cols [128,192)
// ---------------------------------------------------------------------------
__global__ __launch_bounds__(256)
void bcast_k(const uint32_t* __restrict__ krh, const uint32_t* __restrict__ krl,
             uint32_t* __restrict__ kh, uint32_t* __restrict__ kl)
{
    int idx = blockIdx.x * 256 + threadIdx.x;   // B*H*S*32
    int j = idx & 31;
    int s = (idx >> 5) & 2047;
    int h = (idx >> 16) & 15;
    int b = idx >> 20;
    uint32_t src = (uint32_t)((b * Sq + s) * 32 + j);
    size_t dst = ((size_t)((b * Hq + h) * Sq + s)) * 96 + 64 + j;
    kh[dst] = krh[src];
    kl[dst] = krl[src];
}

// ---------------------------------------------------------------------------
// Causal flash attention on mma.sync bf16x3, double-buffered K/V.
// grid (S/128, B*H), 256 threads (8 warps x m16 rows).
// Q-hi resident smem (stride 400, conflict-free), Q-lo in registers.
// K hi/lo + V hi/lo double-buffered, 1-iter cp.async prefetch.
// ---------------------------------------------------------------------------
#define QSTRB 400   // 192 bf16 = 384 B + 16 pad (bank step 4 -> conflict-free)
#define VSTRB 272   // 128 bf16 = 256 B + 16 pad
#define SM_QH 0
#define KBUF0 51200         // each K buf: KH (25600) + KL (25600)
#define VBUF0 153600        // each V buf: VH (17408) + VL (17408)
#define ATTN_SMEM 223232

__global__ __launch_bounds__(256, 1)
void attn_mma(const __nv_bfloat16* __restrict__ qh_, const __nv_bfloat16* __restrict__ ql_,
              const __nv_bfloat16* __restrict__ kh_, const __nv_bfloat16* __restrict__ kl_,
              const __nv_bfloat16* __restrict__ vh_, const __nv_bfloat16* __restrict__ vl_,
              float* __restrict__ O)
{
    extern __shared__ __align__(16) char sm[];
    const uint32_t sb = smem_u32(sm);

    const int bh = blockIdx.y;
    const int b = bh >> 4, h = bh & 15;
    const int s0 = ((int)gridDim.x - 1 - (int)blockIdx.x) * 128;
    const int tid = threadIdx.x, wid = tid >> 5, lane = tid & 31;
    const int warp_m = wid * 16;
    const int g = lane >> 2, c2 = (lane & 3) * 2;

    const size_t qkb = (size_t)bh * Sq * DQK;
    const size_t vb  = (size_t)bh * Sq * DVq;

    const uint32_t a_off = (uint32_t)((warp_m + (lane & 15)) * QSTRB + ((lane >> 4) << 4));
    const uint32_t b_off = (uint32_t)(((lane & 7) + ((lane >> 4) << 3)) * QSTRB +
                                      (((lane >> 3) & 1) << 4));
    const uint32_t v_off = (uint32_t)((lane & 15) * VSTRB + ((lane >> 4) << 4));

    // ---- stage Q-hi (resident) and Q-lo (via K buf 0) ----
    {
        const __nv_bfloat16* sh = qh_ + qkb + (size_t)s0 * DQK;
        const __nv_bfloat16* sl = ql_ + qkb + (size_t)s0 * DQK;
#pragma unroll
        for (int j = 0; j < 12; j++) {
            int e = tid + j * 256;            // 0..3071
            int r = e / 24, s = e - r * 24;
            cp16(sb + SM_QH + r * QSTRB + s * 16, sh + r * 192 + s * 8);
            cp16(sb + KBUF0 + r * QSTRB + s * 16, sl + r * 192 + s * 8);
        }
        CP_COMMIT();
        CP_WAIT(0);
        __syncthreads();
    }

    // ---- Q-lo fragments -> registers (48 regs) ----
    uint32_t qlo[12][4];
#pragma unroll
    for (int ks = 0; ks < 12; ks++)
        ldm4(qlo[ks], sb + KBUF0 + a_off + ks * 32);
    __syncthreads();   // staging area free for K(0)

    // ---- K/V tile loader ----
    auto load_kv = [&](int jb, int buf) {
        const uint32_t kb = sb + KBUF0 + buf * 51200;
        const uint32_t vbuf = sb + VBUF0 + buf * 34816;
        const __nv_bfloat16* skh = kh_ + qkb + (size_t)(jb * 64) * DQK;
        const __nv_bfloat16* skl = kl_ + qkb + (size_t)(jb * 64) * DQK;
        const __nv_bfloat16* svh = vh_ + vb + (size_t)(jb * 64) * DVq;
        const __nv_bfloat16* svl = vl_ + vb + (size_t)(jb * 64) * DVq;
#pragma unroll
        for (int j = 0; j < 6; j++) {
            int e = tid + j * 256;            // 0..1535
            int r = e / 24, s = e - r * 24;
            cp16(kb + r * QSTRB + s * 16, skh + r * 192 + s * 8);
            cp16(kb + 25600 + r * QSTRB + s * 16, skl + r * 192 + s * 8);
        }
#pragma unroll
        for (int j = 0; j < 4; j++) {
            int e = tid + j * 256;            // 0..1023
            int r = e >> 4, s = e & 15;
            cp16(vbuf + r * VSTRB + s * 16, svh + r * 128 + s * 8);
            cp16(vbuf + 17408 + r * VSTRB + s * 16, svl + r * 128 + s * 8);
        }
        CP_COMMIT();
    };

    const int jmax = (s0 >> 6) + 1;
    load_kv(0, 0);

    float accO[16][4];
#pragma unroll
    for (int nf = 0; nf < 16; nf++)
#pragma unroll
        for (int j = 0; j < 4; j++) accO[nf][j] = 0.f;
    float m0 = -INFINITY, m1 = -INFINITY, l0 = 0.f, l1 = 0.f;

    const float scale = 0.07216878364870322f;   // 1/sqrt(192)
    const int row0 = s0 + warp_m + g;
    const int row1 = row0 + 8;

    for (int jb = 0; jb <= jmax; jb++) {
        const int buf = jb & 1;
        if (jb < jmax) {
            load_kv(jb + 1, buf ^ 1);
            CP_WAIT(1);
        } else {
            CP_WAIT(0);
        }
        __syncthreads();

        const uint32_t kb = sb + KBUF0 + buf * 51200;
        const uint32_t vbuf = sb + VBUF0 + buf * 34816;

        // ---- S = Q K^T (bf16x3; Q-lo from registers) ----
        float S[8][4];
#pragma unroll
        for (int nf = 0; nf < 8; nf++)
#pragma unroll
            for (int j = 0; j < 4; j++) S[nf][j] = 0.f;

#pragma unroll
        for (int ks = 0; ks < 12; ks++) {
            uint32_t ah[4];
            ldm4(ah, sb + SM_QH + a_off + ks * 32);
#pragma unroll
            for (int p = 0; p < 4; p++) {
                uint32_t bv[4];
                ldm4(bv, kb + b_off + p * 16 * QSTRB + ks * 32);
                mma16816(S[2*p],   ah, bv);
                mma16816(S[2*p+1], ah, bv + 2);
                mma16816(S[2*p],   qlo[ks], bv);
                mma16816(S[2*p+1], qlo[ks], bv + 2);
            }
#pragma unroll
            for (int p = 0; p < 4; p++) {
                uint32_t bv[4];
                ldm4(bv, kb + 25600 + b_off + p * 16 * QSTRB + ks * 32);
                mma16816(S[2*p],   ah, bv);
                mma16816(S[2*p+1], ah, bv + 2);
            }
        }

        // ---- scale + causal mask ----
        const bool domask = ((jb << 6) + 63) > row0;
#pragma unroll
        for (int nf = 0; nf < 8; nf++) {
#pragma unroll
            for (int j = 0; j < 4; j++) S[nf][j] *= scale;
            if (domask) {
                int key0 = (jb << 6) + nf * 8 + c2;
                if (key0     > row0) S[nf][0] = -INFINITY;
                if (key0 + 1 > row0) S[nf][1] = -INFINITY;
                if (key0     > row1) S[nf][2] = -INFINITY;
                if (key0 + 1 > row1) S[nf][3] = -INFINITY;
            }
        }

        // ---- online softmax (rows g and g+8; quad-local reductions) ----
        float rm0 = -INFINITY, rm1 = -INFINITY;
#pragma unroll
        for (int nf = 0; nf < 8; nf++) {
            rm0 = fmaxf(rm0, fmaxf(S[nf][0], S[nf][1]));
            rm1 = fmaxf(rm1, fmaxf(S[nf][2], S[nf][3]));
        }
        rm0 = fmaxf(rm0, __shfl_xor_sync(0xffffffffu, rm0, 1));
        rm0 = fmaxf(rm0, __shfl_xor_sync(0xffffffffu, rm0, 2));
        rm1 = fmaxf(rm1, __shfl_xor_sync(0xffffffffu, rm1, 1));
        rm1 = fmaxf(rm1, __shfl_xor_sync(0xffffffffu, rm1, 2));

        float mn0 = fmaxf(m0, rm0), mn1 = fmaxf(m1, rm1);
        float al0 = __expf(m0 - mn0), al1 = __expf(m1 - mn1);
        m0 = mn0; m1 = mn1;

        float rs0 = 0.f, rs1 = 0.f;
#pragma unroll
        for (int nf = 0; nf < 8; nf++) {
            S[nf][0] = __expf(S[nf][0] - mn0);
            S[nf][1] = __expf(S[nf][1] - mn0);
            S[nf][2] = __expf(S[nf][2] - mn1);
            S[nf][3] = __expf(S[nf][3] - mn1);
            rs0 += S[nf][0] + S[nf][1];
            rs1 += S[nf][2] + S[nf][3];
        }
        rs0 += __shfl_xor_sync(0xffffffffu, rs0, 1);
        rs0 += __shfl_xor_sync(0xffffffffu, rs0, 2);
        rs1 += __shfl_xor_sync(0xffffffffu, rs1, 1);
        rs1 += __shfl_xor_sync(0xffffffffu, rs1, 2);
        l0 = l0 * al0 + rs0;
        l1 = l1 * al1 + rs1;

        // ---- rescale O acc ----
#pragma unroll
        for (int nf = 0; nf < 16; nf++) {
            accO[nf][0] *= al0; accO[nf][1] *= al0;
            accO[nf][2] *= al1; accO[nf][3] *= al1;
        }

        // ---- pack P fragments (hi/lo) ----
        uint32_t ph[4][4], pl[4][4];
#pragma unroll
        for (int t = 0; t < 4; t++) {
            float v00 = S[2*t][0],   v01 = S[2*t][1];
            float v10 = S[2*t][2],   v11 = S[2*t][3];
            float v20 = S[2*t+1][0], v21 = S[2*t+1][1];
            float v30 = S[2*t+1][2], v31 = S[2*t+1][3];
            ph[t][0] = packbf(v00, v01);
            ph[t][1] = packbf(v10, v11);
            ph[t][2] = packbf(v20, v21);
            ph[t][3] = packbf(v30, v31);
            __nv_bfloat162 h0 = *(__nv_bfloat162*)&ph[t][0];
            __nv_bfloat162 h1 = *(__nv_bfloat162*)&ph[t][1];
            __nv_bfloat162 h2 = *(__nv_bfloat162*)&ph[t][2];
            __nv_bfloat162 h3 = *(__nv_bfloat162*)&ph[t][3];
            pl[t][0] = packbf(v00 - __low2float(h0), v01 - __high2float(h0));
            pl[t][1] = packbf(v10 - __low2float(h1), v11 - __high2float(h1));
            pl[t][2] = packbf(v20 - __low2float(h2), v21 - __high2float(h2));
            pl[t][3] = packbf(v30 - __low2float(h3), v31 - __high2float(h3));
        }

        // ---- O += P V (bf16x3); V^T operand via trans ldmatrix ----
#pragma unroll
        for (int t = 0; t < 4; t++) {
#pragma unroll
            for (int p = 0; p < 8; p++) {
                uint32_t bv[4];
                ldm4t(bv, vbuf + v_off + t * 16 * VSTRB + p * 32);
                mma16816(accO[2*p],   ph[t], bv);
                mma16816(accO[2*p+1], ph[t], bv + 2);
                mma16816(accO[2*p],   pl[t], bv);
                mma16816(accO[2*p+1], pl[t], bv + 2);
                ldm4t(bv, vbuf + 17408 + v_off + t * 16 * VSTRB + p * 32);
                mma16816(accO[2*p],   ph[t], bv);
                mma16816(accO[2*p+1], ph[t], bv + 2);
            }
        }
        __syncthreads();   // all warps done with this buf before it is refilled
    }

    // ---- epilogue ----
    float inv0 = 1.0f / l0, inv1 = 1.0f / l1;
#pragma unroll
    for (int nf = 0; nf < 16; nf++) {
        int col = h * DVq + nf * 8 + c2;
        size_t o0 = ((size_t)(b * Sq + row0)) * (size_t)(Hq * DVq) + col;
        size_t o1 = ((size_t)(b * Sq + row1)) * (size_t)(Hq * DVq) + col;
        *(float2*)(O + o0) = make_float2(accO[nf][0] * inv0, accO[nf][1] * inv0);
        *(float2*)(O + o1) = make_float2(accO[nf][2] * inv1, accO[nf][3] * inv1);
    }
}

// ---------------------------------------------------------------------------
extern "C" void kernel_launch(void* const* d_in, const int* in_sizes, int n_in,
                              void* d_out, int out_size)
{
    (void)in_sizes; (void)n_in; (void)out_size;
    const float* x    = (const float*)d_in[0];
    const float* W_c  = (const float*)d_in[1];
    const float* W_cp = (const float*)d_in[2];
    const float* W_qc = (const float*)d_in[3];
    const float* W_qr = (const float*)d_in[4];
    const float* W_kc = (const float*)d_in[5];
    const float* W_kr = (const float*)d_in[6];
    const float* W_v  = (const float*)d_in[7];
    float* out = (float*)d_out;

    char* arena;
    cudaGetSymbolAddress((void**)&arena, g_arena);
    __nv_bfloat16* xhi   = (__nv_bfloat16*)(arena + O_XHI);
    __nv_bfloat16* xlo   = (__nv_bfloat16*)(arena + O_XLO);
    __nv_bfloat16* WcTh  = (__nv_bfloat16*)(arena + O_WCTH);
    __nv_bfloat16* WcTl  = (__nv_bfloat16*)(arena + O_WCTL);
    __nv_bfloat16* WcpTh = (__nv_bfloat16*)(arena + O_WCPTH);
    __nv_bfloat16* WcpTl = (__nv_bfloat16*)(arena + O_WCPTL);
    __nv_bfloat16* WqcTh = (__nv_bfloat16*)(arena + O_WQCTH);
    __nv_bfloat16* WqcTl = (__nv_bfloat16*)(arena + O_WQCTL);
    __nv_bfloat16* WqrTh = (__nv_bfloat16*)(arena + O_WQRTH);
    __nv_bfloat16* WqrTl = (__nv_bfloat16*)(arena + O_WQRTL);
    __nv_bfloat16* WkcTh = (__nv_bfloat16*)(arena + O_WKCTH);
    __nv_bfloat16* WkcTl = (__nv_bfloat16*)(arena + O_WKCTL);
    __nv_bfloat16* WkrTh = (__nv_bfloat16*)(arena + O_WKRTH);
    __nv_bfloat16* WkrTl = (__nv_bfloat16*)(arena + O_WKRTL);
    __nv_bfloat16* WvTh  = (__nv_bfloat16*)(arena + O_WVTH);
    __nv_bfloat16* WvTl  = (__nv_bfloat16*)(arena + O_WVTL);
    __nv_bfloat16* chi   = (__nv_bfloat16*)(arena + O_CHI);
    __nv_bfloat16* clo   = (__nv_bfloat16*)(arena + O_CLO);
    __nv_bfloat16* cphi  = (__nv_bfloat16*)(arena + O_CPHI);
    __nv_bfloat16* cplo  = (__nv_bfloat16*)(arena + O_CPLO);
    __nv_bfloat16* krh   = (__nv_bfloat16*)(arena + O_KRH);
    __nv_bfloat16* krl   = (__nv_bfloat16*)(arena + O_KRL);
    __nv_bfloat16* qh    = (__nv_bfloat16*)(arena + O_QH);
    __nv_bfloat16* ql    = (__nv_bfloat16*)(arena + O_QL);
    __nv_bfloat16* kh    = (__nv_bfloat16*)(arena + O_KH);
    __nv_bfloat16* kl    = (__nv_bfloat16*)(arena + O_KL);
    __nv_bfloat16* vh    = (__nv_bfloat16*)(arena + O_VH);
    __nv_bfloat16* vl    = (__nv_bfloat16*)(arena + O_VL);

    const int GSM128 = 2 * (128 * 144 + 128 * 144);  // 73728
    const int GSM64  = 2 * (128 * 144 +  64 * 144);  // 55296
    cudaFuncSetAttribute(mma_gemm<128>, cudaFuncAttributeMaxDynamicSharedMemorySize, GSM128);
    cudaFuncSetAttribute(mma_gemm<64>,  cudaFuncAttributeMaxDynamicSharedMemorySize, GSM64);
    cudaFuncSetAttribute(attn_mma, cudaFuncAttributeMaxDynamicSharedMemorySize, ATTN_SMEM);

    // fp32 -> bf16 hi/lo splits
    split_f32<<<32768, 256>>>(x, xhi, xlo);
    tsplit<<<dim3(16, 64, 1),  dim3(32, 8)>>>(W_c,  WcTh,  WcTl,  2048, 512);
    tsplit<<<dim3(32, 64, 1),  dim3(32, 8)>>>(W_cp, WcpTh, WcpTl, 2048, 1024);
    tsplit<<<dim3( 4, 32, 16), dim3(32, 8)>>>(W_qc, WqcTh, WqcTl, 1024, 128);
    tsplit<<<dim3( 2, 32, 16), dim3(32, 8)>>>(W_qr, WqrTh, WqrTl, 1024, 64);
    tsplit<<<dim3( 4, 16, 16), dim3(32, 8)>>>(W_kc, WkcTh, WkcTl, 512, 128);
    tsplit<<<dim3( 2, 64, 1),  dim3(32, 8)>>>(W_kr, WkrTh, WkrTl, 2048, 64);
    tsplit<<<dim3( 4, 16, 16), dim3(32, 8)>>>(W_v,  WvTh,  WvTl,  512, 128);

    // projections (bf16x3 mma.sync)
    mma_gemm<128><<<dim3(4, 32, 1),  256, GSM128>>>(xhi, xlo, WcTh, WcTl, nullptr, chi, clo,
                                                    2048, 512, 2, 0, 0);
    mma_gemm<128><<<dim3(8, 32, 1),  256, GSM128>>>(xhi, xlo, WcpTh, WcpTl, nullptr, cphi, cplo,
                                                    2048, 1024, 2, 0, 0);
    mma_gemm<64> <<<dim3(1, 32, 1),  256, GSM64 >>>(xhi, xlo, WkrTh, WkrTl, nullptr, krh, krl,
                                                    2048, 64, 2, 0, 0);
    mma_gemm<128><<<dim3(1, 32, 16), 256, GSM128>>>(cphi, cplo, WqcTh, WqcTl, nullptr, qh, ql,
                                                    1024, 128, 3, 0, DQK);
    mma_gemm<64> <<<dim3(1, 32, 16), 256, GSM64 >>>(cphi, cplo, WqrTh, WqrTl, nullptr, qh, ql,
                                                    1024, 64, 3, 128, DQK);
    mma_gemm<128><<<dim3(1, 32, 16), 256, GSM128>>>(chi, clo, WkcTh, WkcTl, nullptr, kh, kl,
                                                    512, 128, 3, 0, DQK);
    mma_gemm<128><<<dim3(1, 32, 16), 256, GSM128>>>(chi, clo, WvTh, WvTl, nullptr, vh, vl,
                                                    512, 128, 3, 0, DVq);

    bcast_k<<<(Bq*Hq*Sq*32) / 256, 256>>>((const uint32_t*)krh, (const uint32_t*)krl,
                                          (uint32_t*)kh, (uint32_t*)kl);
    attn_mma<<<dim3(Sq / 128, Bq * Hq), 256, ATTN_SMEM>>>(qh, ql, kh, kl, vh, vl, out);
}

// round 6
// speedup vs baseline: 5.0234x; 1.3128x over previous
#include <cuda_runtime.h>
#include <cuda_fp16.h>
#include <math.h>
#include <stdint.h>

// Problem constants
#define Bq   2
#define Sq   2048
#define DIMq 2048
#define Hq   16
#define DKq  128
#define DRq  64
#define DCq  512
#define DCPq 1024
#define DVq  128
#define DQK  192
#define Mrows (Bq*Sq)      // 4096

// ------------------------- scratch arena (bss) ------------------------------
#define O_XHI    0ULL
#define O_XLO    16777216ULL
#define O_WCTH   33554432ULL
#define O_WCTL   35651584ULL
#define O_WCPTH  37748736ULL
#define O_WCPTL  41943040ULL
#define O_WQCTH  46137344ULL
#define O_WQCTL  50331648ULL
#define O_WQRTH  54525952ULL
#define O_WQRTL  56623104ULL
#define O_WKCTH  58720256ULL
#define O_WKCTL  60817408ULL
#define O_WKRTH  62914560ULL
#define O_WKRTL  63176704ULL
#define O_WVTH   63438848ULL
#define O_WVTL   65536000ULL
#define O_CHI    67633152ULL
#define O_CLO    71827456ULL
#define O_CPHI   76021760ULL
#define O_CPLO   84410368ULL
#define O_KR     92798976ULL    // kr single fp16 [B,S,64]
#define O_QH     93847552ULL    // q hi  [B,H,S,192]
#define O_QL     119013376ULL   // q lo
#define O_KS     144179200ULL   // k single [B,H,S,192]
#define O_VS     194510848ULL   // v single [B,H,S,128]
#define ARENA_BYTES 228065280ULL

__device__ __align__(256) char g_arena[ARENA_BYTES];

// ------------------------- helpers ------------------------------------------
__device__ __forceinline__ uint32_t smem_u32(const void* p) {
    uint32_t a;
    asm("{ .reg .u64 t; cvta.to.shared.u64 t, %1; cvt.u32.u64 %0, t; }" : "=r"(a) : "l"(p));
    return a;
}

__device__ __forceinline__ void cp16(uint32_t dst, const void* src) {
    asm volatile("cp.async.cg.shared.global [%0], [%1], 16;" :: "r"(dst), "l"(src));
}
#define CP_COMMIT() asm volatile("cp.async.commit_group;" ::: "memory")
#define CP_WAIT(n)  asm volatile("cp.async.wait_group %0;" :: "n"(n) : "memory")

__device__ __forceinline__ void ldm4(uint32_t* r, uint32_t addr) {
    asm volatile("ldmatrix.sync.aligned.m8n8.x4.shared.b16 {%0,%1,%2,%3}, [%4];"
                 : "=r"(r[0]), "=r"(r[1]), "=r"(r[2]), "=r"(r[3]) : "r"(addr));
}
__device__ __forceinline__ void ldm4t(uint32_t* r, uint32_t addr) {
    asm volatile("ldmatrix.sync.aligned.m8n8.x4.trans.shared.b16 {%0,%1,%2,%3}, [%4];"
                 : "=r"(r[0]), "=r"(r[1]), "=r"(r[2]), "=r"(r[3]) : "r"(addr));
}

__device__ __forceinline__ void mma16816(float* d, const uint32_t* a, const uint32_t* b) {
    asm volatile("mma.sync.aligned.m16n8k16.row.col.f32.f16.f16.f32 "
                 "{%0,%1,%2,%3}, {%4,%5,%6,%7}, {%8,%9}, {%0,%1,%2,%3};"
                 : "+f"(d[0]), "+f"(d[1]), "+f"(d[2]), "+f"(d[3])
                 : "r"(a[0]), "r"(a[1]), "r"(a[2]), "r"(a[3]), "r"(b[0]), "r"(b[1]));
}

__device__ __forceinline__ uint32_t packh2(float x, float y) {
    __half2 t = __floats2half2_rn(x, y);
    return *(uint32_t*)&t;
}

// ---------------------------------------------------------------------------
// split x fp32 -> fp16 hi/lo
// ---------------------------------------------------------------------------
__global__ __launch_bounds__(256)
void split_f32(const float* __restrict__ A, __half* __restrict__ hi,
               __half* __restrict__ lo)
{
    int i = blockIdx.x * 256 + threadIdx.x;
    float v = A[i];
    __half h = __float2half_rn(v);
    hi[i] = h;
    lo[i] = __float2half_rn(v - __half2float(h));
}

// ---------------------------------------------------------------------------
// Transpose + split: W[(h,)k,n] fp32 -> out[(h,)n,k] fp16 hi/lo
// ---------------------------------------------------------------------------
__global__ __launch_bounds__(256)
void tsplit(const float* __restrict__ W, __half* __restrict__ hi,
            __half* __restrict__ lo, int K, int N)
{
    __shared__ float t[32][33];
    const size_t hb = (size_t)blockIdx.z * (size_t)K * (size_t)N;
    const int k0 = blockIdx.y * 32, n0 = blockIdx.x * 32;
    const int x = threadIdx.x, y = threadIdx.y;
#pragma unroll
    for (int i = 0; i < 4; i++)
        t[y + 8*i][x] = W[hb + (size_t)(k0 + y + 8*i) * N + n0 + x];
    __syncthreads();
#pragma unroll
    for (int i = 0; i < 4; i++) {
        float v = t[x][y + 8*i];
        __half h = __float2half_rn(v);
        size_t o = hb + (size_t)(n0 + y + 8*i) * K + k0 + x;
        hi[o] = h;
        lo[o] = __float2half_rn(v - __half2float(h));
    }
}

// ---------------------------------------------------------------------------
// mma.sync fp16x3 GEMM: all 3 terms per k=32 chunk (Ahi,Alo,Bhi,Blo tiles
// loaded once). ROWB=80 (conflict-free). Double-buffered, occupancy 2.
// out_kind: 2 = fp16 hi/lo flat [M][Nfull]
//           3 = fp16 hi/lo per-head [((b*16+h)*2048+s)*out_ld + col_off + n]
//           4 = fp16 single per-head
//           5 = fp16 single flat
// ---------------------------------------------------------------------------
template<int BN>
__global__ __launch_bounds__(256, 2)
void mma_gemm(const __half* __restrict__ Ahi, const __half* __restrict__ Alo,
              const __half* __restrict__ Bhi, const __half* __restrict__ Blo,
              __half* __restrict__ C1, __half* __restrict__ Chi,
              __half* __restrict__ Clo,
              int K, int Nfull, int out_kind, int col_off, int out_ld)
{
    constexpr int ROWB = 80;            // 64 B data + 16 B pad
    constexpr int ABUF = 128 * ROWB;    // 10240 B
    constexpr int BBUF = BN * ROWB;
    constexpr int BUFSZ = 2 * ABUF + 2 * BBUF;
    constexpr int BNW  = BN / 2;
    constexpr int NFR  = BNW / 8;

    extern __shared__ __align__(16) char smg[];

    const int tid  = threadIdx.x;
    const int wid  = tid >> 5;
    const int lane = tid & 31;
    const int m_blk = blockIdx.y * 128;
    const int n_blk = blockIdx.x * BN;
    const int head  = blockIdx.z;
    const int warp_m = (wid >> 1) * 32;
    const int warp_n = (wid & 1) * BNW;

    const size_t bhead = (size_t)head * (size_t)Nfull * (size_t)K;
    const __half* Bh = Bhi + bhead;
    const __half* Bl = Blo + bhead;

    const uint32_t sb = smem_u32(smg);
    const int KC = K >> 5;

    float acc[2][NFR][4];
#pragma unroll
    for (int mi = 0; mi < 2; mi++)
#pragma unroll
        for (int ni = 0; ni < NFR; ni++)
#pragma unroll
            for (int j = 0; j < 4; j++) acc[mi][ni][j] = 0.f;

    auto load_chunk = [&](int i, int buf) {
        const int kt = i << 5;
        const uint32_t db = sb + buf * BUFSZ;
#pragma unroll
        for (int j = 0; j < 2; j++) {
            int e = tid + j * 256;          // 0..511
            int r = e >> 2, s = e & 3;
            size_t g = (size_t)(m_blk + r) * K + kt + s * 8;
            cp16(db + r * ROWB + s * 16, Ahi + g);
            cp16(db + ABUF + r * ROWB + s * 16, Alo + g);
        }
#pragma unroll
        for (int j = 0; j < BN / 64; j++) {
            int e = tid + j * 256;
            int r = e >> 2, s = e & 3;
            size_t g = (size_t)(n_blk + r) * K + kt + s * 8;
            cp16(db + 2 * ABUF + r * ROWB + s * 16, Bh + g);
            cp16(db + 2 * ABUF + BBUF + r * ROWB + s * 16, Bl + g);
        }
        CP_COMMIT();
    };

    load_chunk(0, 0);

    const uint32_t aoff = (uint32_t)((warp_m + (lane & 15)) * ROWB + ((lane >> 4) << 4));
    const uint32_t boff = (uint32_t)((warp_n + (lane & 7) + ((lane >> 4) << 3)) * ROWB +
                                     (((lane >> 3) & 1) << 4));

    for (int i = 0; i < KC; i++) {
        const int buf = i & 1;
        if (i + 1 < KC) {
            load_chunk(i + 1, buf ^ 1);
            CP_WAIT(1);
        } else {
            CP_WAIT(0);
        }
        __syncthreads();

        const uint32_t db = sb + buf * BUFSZ;
#pragma unroll
        for (int ks = 0; ks < 2; ks++) {
            uint32_t ah[2][4], al[2][4];
#pragma unroll
            for (int mi = 0; mi < 2; mi++) {
                ldm4(ah[mi], db + aoff + mi * 16 * ROWB + ks * 32);
                ldm4(al[mi], db + ABUF + aoff + mi * 16 * ROWB + ks * 32);
            }
            // B-hi: Ahi.Bhi + Alo.Bhi
            {
                uint32_t b[NFR][2];
#pragma unroll
                for (int nj = 0; nj < NFR / 2; nj++) {
                    uint32_t r[4];
                    ldm4(r, db + 2 * ABUF + boff + nj * 16 * ROWB + ks * 32);
                    b[2*nj][0] = r[0]; b[2*nj][1] = r[1];
                    b[2*nj+1][0] = r[2]; b[2*nj+1][1] = r[3];
                }
#pragma unroll
                for (int mi = 0; mi < 2; mi++)
#pragma unroll
                    for (int ni = 0; ni < NFR; ni++) {
                        mma16816(acc[mi][ni], ah[mi], b[ni]);
                        mma16816(acc[mi][ni], al[mi], b[ni]);
                    }
            }
            // B-lo: Ahi.Blo
            {
                uint32_t b[NFR][2];
#pragma unroll
                for (int nj = 0; nj < NFR / 2; nj++) {
                    uint32_t r[4];
                    ldm4(r, db + 2 * ABUF + BBUF + boff + nj * 16 * ROWB + ks * 32);
                    b[2*nj][0] = r[0]; b[2*nj][1] = r[1];
                    b[2*nj+1][0] = r[2]; b[2*nj+1][1] = r[3];
                }
#pragma unroll
                for (int mi = 0; mi < 2; mi++)
#pragma unroll
                    for (int ni = 0; ni < NFR; ni++)
                        mma16816(acc[mi][ni], ah[mi], b[ni]);
            }
        }
        __syncthreads();
    }

    const int g = lane >> 2, c2 = (lane & 3) * 2;
#pragma unroll
    for (int mi = 0; mi < 2; mi++) {
#pragma unroll
        for (int ni = 0; ni < NFR; ni++) {
            int col = n_blk + warp_n + ni * 8 + c2;
#pragma unroll
            for (int hrow = 0; hrow < 2; hrow++) {
                int m = m_blk + warp_m + mi * 16 + g + hrow * 8;
                float v0 = acc[mi][ni][hrow * 2];
                float v1 = acc[mi][ni][hrow * 2 + 1];
                if (out_kind == 2 || out_kind == 3) {
                    uint32_t hh = packh2(v0, v1);
                    __half2 h2 = *(__half2*)&hh;
                    uint32_t ll = packh2(v0 - __low2float(h2), v1 - __high2float(h2));
                    size_t o;
                    if (out_kind == 2) {
                        o = (size_t)m * Nfull + col;
                    } else {
                        int b = m >> 11, s = m & 2047;
                        o = ((size_t)((b * Hq + head) * Sq + s)) * out_ld + col_off + col;
                    }
                    *(uint32_t*)(Chi + o) = hh;
                    *(uint32_t*)(Clo + o) = ll;
                } else if (out_kind == 4) {
                    int b = m >> 11, s = m & 2047;
                    size_t o = ((size_t)((b * Hq + head) * Sq + s)) * out_ld + col_off + col;
                    *(uint32_t*)(C1 + o) = packh2(v0, v1);
                } else {   // 5
                    size_t o = (size_t)m * out_ld + col_off + col;
                    *(uint32_t*)(C1 + o) = packh2(v0, v1);
                }
            }
        }
    }
}

// ---------------------------------------------------------------------------
// Broadcast kr fp16 [B,S,64] into k [B,H,S,192] cols [128,192)
// ---------------------------------------------------------------------------
__global__ __launch_bounds__(256)
void bcast_k(const uint32_t* __restrict__ kr, uint32_t* __restrict__ k)
{
    int idx = blockIdx.x * 256 + threadIdx.x;   // B*H*S*32
    int j = idx & 31;
    int s = (idx >> 5) & 2047;
    int h = (idx >> 16) & 15;
    int b = idx >> 20;
    k[((size_t)((b * Hq + h) * Sq + s)) * 96 + 64 + j] = kr[(b * Sq + s) * 32 + j];
}

// ---------------------------------------------------------------------------
// Causal flash attention, fp16 2-term: S = (Qhi+Qlo).K, O = (Phi+Plo).V
// with K, V stored single fp16. grid (S/128, B*H), 256 threads.
// Q-hi resident smem; Q-lo in registers; K/V double-buffered.
// ---------------------------------------------------------------------------
#define QSTRB 400   // 192 fp16 = 384 B + 16 pad
#define VSTRB 272   // 128 fp16 = 256 B + 16 pad
#define KBUF0 51200          // 2 x 25600 (K single)
#define VBUF0 102400         // 2 x 17408 (V single)
#define ATTN_SMEM 137216

__global__ __launch_bounds__(256, 1)
void attn_mma(const __half* __restrict__ qh_, const __half* __restrict__ ql_,
              const __half* __restrict__ k_, const __half* __restrict__ v_,
              float* __restrict__ O)
{
    extern __shared__ __align__(16) char sm[];
    const uint32_t sb = smem_u32(sm);

    const int bh = blockIdx.y;
    const int b = bh >> 4, h = bh & 15;
    const int s0 = ((int)gridDim.x - 1 - (int)blockIdx.x) * 128;
    const int tid = threadIdx.x, wid = tid >> 5, lane = tid & 31;
    const int warp_m = wid * 16;
    const int g = lane >> 2, c2 = (lane & 3) * 2;

    const size_t qkb = (size_t)bh * Sq * DQK;
    const size_t vb  = (size_t)bh * Sq * DVq;

    const uint32_t a_off = (uint32_t)((warp_m + (lane & 15)) * QSTRB + ((lane >> 4) << 4));
    const uint32_t b_off = (uint32_t)(((lane & 7) + ((lane >> 4) << 3)) * QSTRB +
                                      (((lane >> 3) & 1) << 4));
    const uint32_t v_off = (uint32_t)((lane & 15) * VSTRB + ((lane >> 4) << 4));

    // ---- stage Q-hi (resident) and Q-lo (via K/V buffer area) ----
    {
        const __half* sh = qh_ + qkb + (size_t)s0 * DQK;
        const __half* sl = ql_ + qkb + (size_t)s0 * DQK;
#pragma unroll
        for (int j = 0; j < 12; j++) {
            int e = tid + j * 256;            // 0..3071
            int r = e / 24, s = e - r * 24;
            cp16(sb + r * QSTRB + s * 16, sh + r * 192 + s * 8);
            cp16(sb + KBUF0 + r * QSTRB + s * 16, sl + r * 192 + s * 8);
        }
        CP_COMMIT();
        CP_WAIT(0);
        __syncthreads();
    }

    // ---- Q-lo fragments -> registers (48 regs) ----
    uint32_t qlo[12][4];
#pragma unroll
    for (int ks = 0; ks < 12; ks++)
        ldm4(qlo[ks], sb + KBUF0 + a_off + ks * 32);
    __syncthreads();

    // ---- K/V tile loader (single fp16) ----
    auto load_kv = [&](int jb, int buf) {
        const uint32_t kb = sb + KBUF0 + buf * 25600;
        const uint32_t vbuf = sb + VBUF0 + buf * 17408;
        const __half* sk = k_ + qkb + (size_t)(jb * 64) * DQK;
        const __half* sv = v_ + vb + (size_t)(jb * 64) * DVq;
#pragma unroll
        for (int j = 0; j < 6; j++) {
            int e = tid + j * 256;            // 0..1535
            int r = e / 24, s = e - r * 24;
            cp16(kb + r * QSTRB + s * 16, sk + r * 192 + s * 8);
        }
#pragma unroll
        for (int j = 0; j < 4; j++) {
            int e = tid + j * 256;            // 0..1023
            int r = e >> 4, s = e & 15;
            cp16(vbuf + r * VSTRB + s * 16, sv + r * 128 + s * 8);
        }
        CP_COMMIT();
    };

    const int jmax = (s0 >> 6) + 1;
    load_kv(0, 0);

    float accO[16][4];
#pragma unroll
    for (int nf = 0; nf < 16; nf++)
#pragma unroll
        for (int j = 0; j < 4; j++) accO[nf][j] = 0.f;
    float m0 = -INFINITY, m1 = -INFINITY, l0 = 0.f, l1 = 0.f;

    const float scale = 0.07216878364870322f;   // 1/sqrt(192)
    const int row0 = s0 + warp_m + g;
    const int row1 = row0 + 8;

    for (int jb = 0; jb <= jmax; jb++) {
        const int buf = jb & 1;
        if (jb < jmax) {
            load_kv(jb + 1, buf ^ 1);
            CP_WAIT(1);
        } else {
            CP_WAIT(0);
        }
        __syncthreads();

        const uint32_t kb = sb + KBUF0 + buf * 25600;
        const uint32_t vbuf = sb + VBUF0 + buf * 17408;

        // ---- S = (Qhi + Qlo) K^T ----
        float S[8][4];
#pragma unroll
        for (int nf = 0; nf < 8; nf++)
#pragma unroll
            for (int j = 0; j < 4; j++) S[nf][j] = 0.f;

#pragma unroll
        for (int ks = 0; ks < 12; ks++) {
            uint32_t ah[4];
            ldm4(ah, sb + a_off + ks * 32);
#pragma unroll
            for (int p = 0; p < 4; p++) {
                uint32_t bv[4];
                ldm4(bv, kb + b_off + p * 16 * QSTRB + ks * 32);
                mma16816(S[2*p],   ah, bv);
                mma16816(S[2*p+1], ah, bv + 2);
                mma16816(S[2*p],   qlo[ks], bv);
                mma16816(S[2*p+1], qlo[ks], bv + 2);
            }
        }

        // ---- scale + causal mask ----
        const bool domask = ((jb << 6) + 63) > row0;
#pragma unroll
        for (int nf = 0; nf < 8; nf++) {
#pragma unroll
            for (int j = 0; j < 4; j++) S[nf][j] *= scale;
            if (domask) {
                int key0 = (jb << 6) + nf * 8 + c2;
                if (key0     > row0) S[nf][0] = -INFINITY;
                if (key0 + 1 > row0) S[nf][1] = -INFINITY;
                if (key0     > row1) S[nf][2] = -INFINITY;
                if (key0 + 1 > row1) S[nf][3] = -INFINITY;
            }
        }

        // ---- online softmax ----
        float rm0 = -INFINITY, rm1 = -INFINITY;
#pragma unroll
        for (int nf = 0; nf < 8; nf++) {
            rm0 = fmaxf(rm0, fmaxf(S[nf][0], S[nf][1]));
            rm1 = fmaxf(rm1, fmaxf(S[nf][2], S[nf][3]));
        }
        rm0 = fmaxf(rm0, __shfl_xor_sync(0xffffffffu, rm0, 1));
        rm0 = fmaxf(rm0, __shfl_xor_sync(0xffffffffu, rm0, 2));
        rm1 = fmaxf(rm1, __shfl_xor_sync(0xffffffffu, rm1, 1));
        rm1 = fmaxf(rm1, __shfl_xor_sync(0xffffffffu, rm1, 2));

        float mn0 = fmaxf(m0, rm0), mn1 = fmaxf(m1, rm1);
        float al0 = __expf(m0 - mn0), al1 = __expf(m1 - mn1);
        m0 = mn0; m1 = mn1;

        float rs0 = 0.f, rs1 = 0.f;
#pragma unroll
        for (int nf = 0; nf < 8; nf++) {
            S[nf][0] = __expf(S[nf][0] - mn0);
            S[nf][1] = __expf(S[nf][1] - mn0);
            S[nf][2] = __expf(S[nf][2] - mn1);
            S[nf][3] = __expf(S[nf][3] - mn1);
            rs0 += S[nf][0] + S[nf][1];
            rs1 += S[nf][2] + S[nf][3];
        }
        rs0 += __shfl_xor_sync(0xffffffffu, rs0, 1);
        rs0 += __shfl_xor_sync(0xffffffffu, rs0, 2);
        rs1 += __shfl_xor_sync(0xffffffffu, rs1, 1);
        rs1 += __shfl_xor_sync(0xffffffffu, rs1, 2);
        l0 = l0 * al0 + rs0;
        l1 = l1 * al1 + rs1;

#pragma unroll
        for (int nf = 0; nf < 16; nf++) {
            accO[nf][0] *= al0; accO[nf][1] *= al0;
            accO[nf][2] *= al1; accO[nf][3] *= al1;
        }

        // ---- pack P fragments (hi/lo) ----
        uint32_t ph[4][4], pl[4][4];
#pragma unroll
        for (int t = 0; t < 4; t++) {
            float v00 = S[2*t][0],   v01 = S[2*t][1];
            float v10 = S[2*t][2],   v11 = S[2*t][3];
            float v20 = S[2*t+1][0], v21 = S[2*t+1][1];
            float v30 = S[2*t+1][2], v31 = S[2*t+1][3];
            ph[t][0] = packh2(v00, v01);
            ph[t][1] = packh2(v10, v11);
            ph[t][2] = packh2(v20, v21);
            ph[t][3] = packh2(v30, v31);
            __half2 h0 = *(__half2*)&ph[t][0];
            __half2 h1 = *(__half2*)&ph[t][1];
            __half2 h2 = *(__half2*)&ph[t][2];
            __half2 h3 = *(__half2*)&ph[t][3];
            pl[t][0] = packh2(v00 - __low2float(h0), v01 - __high2float(h0));
            pl[t][1] = packh2(v10 - __low2float(h1), v11 - __high2float(h1));
            pl[t][2] = packh2(v20 - __low2float(h2), v21 - __high2float(h2));
            pl[t][3] = packh2(v30 - __low2float(h3), v31 - __high2float(h3));
        }

        // ---- O += (Phi + Plo) V ----
#pragma unroll
        for (int t = 0; t < 4; t++) {
#pragma unroll
            for (int p = 0; p < 8; p++) {
                uint32_t bv[4];
                ldm4t(bv, vbuf + v_off + t * 16 * VSTRB + p * 32);
                mma16816(accO[2*p],   ph[t], bv);
                mma16816(accO[2*p+1], ph[t], bv + 2);
                mma16816(accO[2*p],   pl[t], bv);
                mma16816(accO[2*p+1], pl[t], bv + 2);
            }
        }
        __syncthreads();
    }

    // ---- epilogue ----
    float inv0 = 1.0f / l0, inv1 = 1.0f / l1;
#pragma unroll
    for (int nf = 0; nf < 16; nf++) {
        int col = h * DVq + nf * 8 + c2;
        size_t o0 = ((size_t)(b * Sq + row0)) * (size_t)(Hq * DVq) + col;
        size_t o1 = ((size_t)(b * Sq + row1)) * (size_t)(Hq * DVq) + col;
        *(float2*)(O + o0) = make_float2(accO[nf][0] * inv0, accO[nf][1] * inv0);
        *(float2*)(O + o1) = make_float2(accO[nf][2] * inv1, accO[nf][3] * inv1);
    }
}

// ---------------------------------------------------------------------------
extern "C" void kernel_launch(void* const* d_in, const int* in_sizes, int n_in,
                              void* d_out, int out_size)
{
    (void)in_sizes; (void)n_in; (void)out_size;
    const float* x    = (const float*)d_in[0];
    const float* W_c  = (const float*)d_in[1];
    const float* W_cp = (const float*)d_in[2];
    const float* W_qc = (const float*)d_in[3];
    const float* W_qr = (const float*)d_in[4];
    const float* W_kc = (const float*)d_in[5];
    const float* W_kr = (const float*)d_in[6];
    const float* W_v  = (const float*)d_in[7];
    float* out = (float*)d_out;

    char* arena;
    cudaGetSymbolAddress((void**)&arena, g_arena);
    __half* xhi   = (__half*)(arena + O_XHI);
    __half* xlo   = (__half*)(arena + O_XLO);
    __half* WcTh  = (__half*)(arena + O_WCTH);
    __half* WcTl  = (__half*)(arena + O_WCTL);
    __half* WcpTh = (__half*)(arena + O_WCPTH);
    __half* WcpTl = (__half*)(arena + O_WCPTL);
    __half* WqcTh = (__half*)(arena + O_WQCTH);
    __half* WqcTl = (__half*)(arena + O_WQCTL);
    __half* WqrTh = (__half*)(arena + O_WQRTH);
    __half* WqrTl = (__half*)(arena + O_WQRTL);
    __half* WkcTh = (__half*)(arena + O_WKCTH);
    __half* WkcTl = (__half*)(arena + O_WKCTL);
    __half* WkrTh = (__half*)(arena + O_WKRTH);
    __half* WkrTl = (__half*)(arena + O_WKRTL);
    __half* WvTh  = (__half*)(arena + O_WVTH);
    __half* WvTl  = (__half*)(arena + O_WVTL);
    __half* chi   = (__half*)(arena + O_CHI);
    __half* clo   = (__half*)(arena + O_CLO);
    __half* cphi  = (__half*)(arena + O_CPHI);
    __half* cplo  = (__half*)(arena + O_CPLO);
    __half* kr    = (__half*)(arena + O_KR);
    __half* qh    = (__half*)(arena + O_QH);
    __half* ql    = (__half*)(arena + O_QL);
    __half* ks    = (__half*)(arena + O_KS);
    __half* vs    = (__half*)(arena + O_VS);

    const int GSM128 = 2 * (2 * 10240 + 2 * 128 * 80);  // 81920
    const int GSM64  = 2 * (2 * 10240 + 2 * 64 * 80);   // 61440
    cudaFuncSetAttribute(mma_gemm<128>, cudaFuncAttributeMaxDynamicSharedMemorySize, GSM128);
    cudaFuncSetAttribute(mma_gemm<64>,  cudaFuncAttributeMaxDynamicSharedMemorySize, GSM64);
    cudaFuncSetAttribute(attn_mma, cudaFuncAttributeMaxDynamicSharedMemorySize, ATTN_SMEM);

    // fp32 -> fp16 hi/lo splits
    split_f32<<<32768, 256>>>(x, xhi, xlo);
    tsplit<<<dim3(16, 64, 1),  dim3(32, 8)>>>(W_c,  WcTh,  WcTl,  2048, 512);
    tsplit<<<dim3(32, 64, 1),  dim3(32, 8)>>>(W_cp, WcpTh, WcpTl, 2048, 1024);
    tsplit<<<dim3( 4, 32, 16), dim3(32, 8)>>>(W_qc, WqcTh, WqcTl, 1024, 128);
    tsplit<<<dim3( 2, 32, 16), dim3(32, 8)>>>(W_qr, WqrTh, WqrTl, 1024, 64);
    tsplit<<<dim3( 4, 16, 16), dim3(32, 8)>>>(W_kc, WkcTh, WkcTl, 512, 128);
    tsplit<<<dim3( 2, 64, 1),  dim3(32, 8)>>>(W_kr, WkrTh, WkrTl, 2048, 64);
    tsplit<<<dim3( 4, 16, 16), dim3(32, 8)>>>(W_v,  WvTh,  WvTl,  512, 128);

    // projections (fp16x3 mma.sync)
    mma_gemm<128><<<dim3(4, 32, 1),  256, GSM128>>>(xhi, xlo, WcTh, WcTl, nullptr, chi, clo,
                                                    2048, 512, 2, 0, 0);
    mma_gemm<128><<<dim3(8, 32, 1),  256, GSM128>>>(xhi, xlo, WcpTh, WcpTl, nullptr, cphi, cplo,
                                                    2048, 1024, 2, 0, 0);
    mma_gemm<64> <<<dim3(1, 32, 1),  256, GSM64 >>>(xhi, xlo, WkrTh, WkrTl, kr, nullptr, nullptr,
                                                    2048, 64, 5, 0, 64);
    mma_gemm<128><<<dim3(1, 32, 16), 256, GSM128>>>(cphi, cplo, WqcTh, WqcTl, nullptr, qh, ql,
                                                    1024, 128, 3, 0, DQK);
    mma_gemm<64> <<<dim3(1, 32, 16), 256, GSM64 >>>(cphi, cplo, WqrTh, WqrTl, nullptr, qh, ql,
                                                    1024, 64, 3, 128, DQK);
    mma_gemm<128><<<dim3(1, 32, 16), 256, GSM128>>>(chi, clo, WkcTh, WkcTl, ks, nullptr, nullptr,
                                                    512, 128, 4, 0, DQK);
    mma_gemm<128><<<dim3(1, 32, 16), 256, GSM128>>>(chi, clo, WvTh, WvTl, vs, nullptr, nullptr,
                                                    512, 128, 4, 0, DVq);

    bcast_k<<<(Bq*Hq*Sq*32) / 256, 256>>>((const uint32_t*)kr, (uint32_t*)ks);
    attn_mma<<<dim3(Sq / 128, Bq * Hq), 256, ATTN_SMEM>>>(qh, ql, ks, vs, out);
}

// round 7
// speedup vs baseline: 6.1788x; 1.2300x over previous
#include <cuda_runtime.h>
#include <cuda_fp16.h>
#include <math.h>
#include <stdint.h>

// Problem constants
#define Bq   2
#define Sq   2048
#define DIMq 2048
#define Hq   16
#define DKq  128
#define DRq  64
#define DCq  512
#define DCPq 1024
#define DVq  128
#define DQK  192
#define Mrows (Bq*Sq)      // 4096

// ------------------------- scratch arena (bss) ------------------------------
#define O_XHI    0ULL
#define O_XLO    16777216ULL
#define O_WCT    33554432ULL
#define O_WCPT   37748736ULL
#define O_WQCT   46137344ULL
#define O_WQRT   54525952ULL
#define O_WKCT   58720256ULL
#define O_WKRT   62914560ULL
#define O_WVT    63438848ULL
#define O_CHI    67633152ULL
#define O_CLO    71827456ULL
#define O_CPHI   76021760ULL
#define O_CPLO   84410368ULL
#define O_KR     92798976ULL    // kr single fp16 [B,S,64]
#define O_QH     93847552ULL    // q hi  [B,H,S,192]
#define O_QL     119013376ULL   // q lo
#define O_KS     144179200ULL   // k single [B,H,S,192]
#define O_VS     194510848ULL   // v single [B,H,S,128]
#define ARENA_BYTES 228065280ULL

__device__ __align__(256) char g_arena[ARENA_BYTES];

// ------------------------- helpers ------------------------------------------
__device__ __forceinline__ uint32_t smem_u32(const void* p) {
    uint32_t a;
    asm("{ .reg .u64 t; cvta.to.shared.u64 t, %1; cvt.u32.u64 %0, t; }" : "=r"(a) : "l"(p));
    return a;
}

__device__ __forceinline__ void cp16(uint32_t dst, const void* src) {
    asm volatile("cp.async.cg.shared.global [%0], [%1], 16;" :: "r"(dst), "l"(src));
}
#define CP_COMMIT() asm volatile("cp.async.commit_group;" ::: "memory")
#define CP_WAIT(n)  asm volatile("cp.async.wait_group %0;" :: "n"(n) : "memory")

__device__ __forceinline__ void ldm4(uint32_t* r, uint32_t addr) {
    asm volatile("ldmatrix.sync.aligned.m8n8.x4.shared.b16 {%0,%1,%2,%3}, [%4];"
                 : "=r"(r[0]), "=r"(r[1]), "=r"(r[2]), "=r"(r[3]) : "r"(addr));
}
__device__ __forceinline__ void ldm4t(uint32_t* r, uint32_t addr) {
    asm volatile("ldmatrix.sync.aligned.m8n8.x4.trans.shared.b16 {%0,%1,%2,%3}, [%4];"
                 : "=r"(r[0]), "=r"(r[1]), "=r"(r[2]), "=r"(r[3]) : "r"(addr));
}

__device__ __forceinline__ void mma16816(float* d, const uint32_t* a, const uint32_t* b) {
    asm volatile("mma.sync.aligned.m16n8k16.row.col.f32.f16.f16.f32 "
                 "{%0,%1,%2,%3}, {%4,%5,%6,%7}, {%8,%9}, {%0,%1,%2,%3};"
                 : "+f"(d[0]), "+f"(d[1]), "+f"(d[2]), "+f"(d[3])
                 : "r"(a[0]), "r"(a[1]), "r"(a[2]), "r"(a[3]), "r"(b[0]), "r"(b[1]));
}

__device__ __forceinline__ uint32_t packh2(float x, float y) {
    __half2 t = __floats2half2_rn(x, y);
    return *(uint32_t*)&t;
}

// ---------------------------------------------------------------------------
// split x fp32 -> fp16 hi/lo
// ---------------------------------------------------------------------------
__global__ __launch_bounds__(256)
void split_f32(const float* __restrict__ A, __half* __restrict__ hi,
               __half* __restrict__ lo)
{
    int i = blockIdx.x * 256 + threadIdx.x;
    float v = A[i];
    __half h = __float2half_rn(v);
    hi[i] = h;
    lo[i] = __float2half_rn(v - __half2float(h));
}

// ---------------------------------------------------------------------------
// Transpose + round: W[(h,)k,n] fp32 -> out[(h,)n,k] fp16 single
// ---------------------------------------------------------------------------
__global__ __launch_bounds__(256)
void tround(const float* __restrict__ W, __half* __restrict__ out, int K, int N)
{
    __shared__ float t[32][33];
    const size_t hb = (size_t)blockIdx.z * (size_t)K * (size_t)N;
    const int k0 = blockIdx.y * 32, n0 = blockIdx.x * 32;
    const int x = threadIdx.x, y = threadIdx.y;
#pragma unroll
    for (int i = 0; i < 4; i++)
        t[y + 8*i][x] = W[hb + (size_t)(k0 + y + 8*i) * N + n0 + x];
    __syncthreads();
#pragma unroll
    for (int i = 0; i < 4; i++)
        out[hb + (size_t)(n0 + y + 8*i) * K + k0 + x] = __float2half_rn(t[x][y + 8*i]);
}

// ---------------------------------------------------------------------------
// mma.sync fp16 2-term GEMM: C = (Ahi+Alo) * W16.
// ROWB=80 conflict-free, double-buffered, occupancy 2.
// out_kind: 2 = fp16 hi/lo flat [M][Nfull]
//           3 = fp16 hi/lo per-head [((b*16+h)*2048+s)*out_ld + col_off + n]
//           4 = fp16 single per-head
//           5 = fp16 single flat
// ---------------------------------------------------------------------------
template<int BN>
__global__ __launch_bounds__(256, 2)
void mma_gemm(const __half* __restrict__ Ahi, const __half* __restrict__ Alo,
              const __half* __restrict__ Bw,
              __half* __restrict__ C1, __half* __restrict__ Chi,
              __half* __restrict__ Clo,
              int K, int Nfull, int out_kind, int col_off, int out_ld)
{
    constexpr int ROWB = 80;            // 64 B data + 16 B pad
    constexpr int ABUF = 128 * ROWB;    // 10240 B
    constexpr int BBUF = BN * ROWB;
    constexpr int BUFSZ = 2 * ABUF + BBUF;
    constexpr int BNW  = BN / 2;
    constexpr int NFR  = BNW / 8;

    extern __shared__ __align__(16) char smg[];

    const int tid  = threadIdx.x;
    const int wid  = tid >> 5;
    const int lane = tid & 31;
    const int m_blk = blockIdx.y * 128;
    const int n_blk = blockIdx.x * BN;
    const int head  = blockIdx.z;
    const int warp_m = (wid >> 1) * 32;
    const int warp_n = (wid & 1) * BNW;

    const __half* Bp = Bw + (size_t)head * (size_t)Nfull * (size_t)K;

    const uint32_t sb = smem_u32(smg);
    const int KC = K >> 5;

    float acc[2][NFR][4];
#pragma unroll
    for (int mi = 0; mi < 2; mi++)
#pragma unroll
        for (int ni = 0; ni < NFR; ni++)
#pragma unroll
            for (int j = 0; j < 4; j++) acc[mi][ni][j] = 0.f;

    auto load_chunk = [&](int i, int buf) {
        const int kt = i << 5;
        const uint32_t db = sb + buf * BUFSZ;
#pragma unroll
        for (int j = 0; j < 2; j++) {
            int e = tid + j * 256;          // 0..511
            int r = e >> 2, s = e & 3;
            size_t g = (size_t)(m_blk + r) * K + kt + s * 8;
            cp16(db + r * ROWB + s * 16, Ahi + g);
            cp16(db + ABUF + r * ROWB + s * 16, Alo + g);
        }
#pragma unroll
        for (int j = 0; j < BN / 64; j++) {
            int e = tid + j * 256;
            int r = e >> 2, s = e & 3;
            cp16(db + 2 * ABUF + r * ROWB + s * 16,
                 Bp + (size_t)(n_blk + r) * K + kt + s * 8);
        }
        CP_COMMIT();
    };

    load_chunk(0, 0);

    const uint32_t aoff = (uint32_t)((warp_m + (lane & 15)) * ROWB + ((lane >> 4) << 4));
    const uint32_t boff = (uint32_t)((warp_n + (lane & 7) + ((lane >> 4) << 3)) * ROWB +
                                     (((lane >> 3) & 1) << 4));

    for (int i = 0; i < KC; i++) {
        const int buf = i & 1;
        if (i + 1 < KC) {
            load_chunk(i + 1, buf ^ 1);
            CP_WAIT(1);
        } else {
            CP_WAIT(0);
        }
        __syncthreads();

        const uint32_t db = sb + buf * BUFSZ;
#pragma unroll
        for (int ks = 0; ks < 2; ks++) {
            uint32_t ah[2][4], al[2][4];
#pragma unroll
            for (int mi = 0; mi < 2; mi++) {
                ldm4(ah[mi], db + aoff + mi * 16 * ROWB + ks * 32);
                ldm4(al[mi], db + ABUF + aoff + mi * 16 * ROWB + ks * 32);
            }
            uint32_t b[NFR][2];
#pragma unroll
            for (int nj = 0; nj < NFR / 2; nj++) {
                uint32_t r[4];
                ldm4(r, db + 2 * ABUF + boff + nj * 16 * ROWB + ks * 32);
                b[2*nj][0] = r[0]; b[2*nj][1] = r[1];
                b[2*nj+1][0] = r[2]; b[2*nj+1][1] = r[3];
            }
#pragma unroll
            for (int mi = 0; mi < 2; mi++)
#pragma unroll
                for (int ni = 0; ni < NFR; ni++) {
                    mma16816(acc[mi][ni], ah[mi], b[ni]);
                    mma16816(acc[mi][ni], al[mi], b[ni]);
                }
        }
        __syncthreads();
    }

    const int g = lane >> 2, c2 = (lane & 3) * 2;
#pragma unroll
    for (int mi = 0; mi < 2; mi++) {
#pragma unroll
        for (int ni = 0; ni < NFR; ni++) {
            int col = n_blk + warp_n + ni * 8 + c2;
#pragma unroll
            for (int hrow = 0; hrow < 2; hrow++) {
                int m = m_blk + warp_m + mi * 16 + g + hrow * 8;
                float v0 = acc[mi][ni][hrow * 2];
                float v1 = acc[mi][ni][hrow * 2 + 1];
                if (out_kind == 2 || out_kind == 3) {
                    uint32_t hh = packh2(v0, v1);
                    __half2 h2 = *(__half2*)&hh;
                    uint32_t ll = packh2(v0 - __low2float(h2), v1 - __high2float(h2));
                    size_t o;
                    if (out_kind == 2) {
                        o = (size_t)m * Nfull + col;
                    } else {
                        int b = m >> 11, s = m & 2047;
                        o = ((size_t)((b * Hq + head) * Sq + s)) * out_ld + col_off + col;
                    }
                    *(uint32_t*)(Chi + o) = hh;
                    *(uint32_t*)(Clo + o) = ll;
                } else if (out_kind == 4) {
                    int b = m >> 11, s = m & 2047;
                    size_t o = ((size_t)((b * Hq + head) * Sq + s)) * out_ld + col_off + col;
                    *(uint32_t*)(C1 + o) = packh2(v0, v1);
                } else {   // 5
                    size_t o = (size_t)m * out_ld + col_off + col;
                    *(uint32_t*)(C1 + o) = packh2(v0, v1);
                }
            }
        }
    }
}

// ---------------------------------------------------------------------------
// Broadcast kr fp16 [B,S,64] into k [B,H,S,192] cols [128,192)
// ---------------------------------------------------------------------------
__global__ __launch_bounds__(256)
void bcast_k(const uint32_t* __restrict__ kr, uint32_t* __restrict__ k)
{
    int idx = blockIdx.x * 256 + threadIdx.x;   // B*H*S*32
    int j = idx & 31;
    int s = (idx >> 5) & 2047;
    int h = (idx >> 16) & 15;
    int b = idx >> 20;
    k[((size_t)((b * Hq + h) * Sq + s)) * 96 + 64 + j] = kr[(b * Sq + s) * 32 + j];
}

// ---------------------------------------------------------------------------
// Causal flash attention, fp16 2-term: S = (Qhi+Qlo).K, O = (Phi+Plo).V
// with K, V stored single fp16. grid (S/128, B*H), 256 threads.
// Q-hi resident smem; Q-lo in registers; K/V double-buffered.
// ---------------------------------------------------------------------------
#define QSTRB 400   // 192 fp16 = 384 B + 16 pad
#define VSTRB 272   // 128 fp16 = 256 B + 16 pad
#define KBUF0 51200          // 2 x 25600 (K single)
#define VBUF0 102400         // 2 x 17408 (V single)
#define ATTN_SMEM 137216

__global__ __launch_bounds__(256, 1)
void attn_mma(const __half* __restrict__ qh_, const __half* __restrict__ ql_,
              const __half* __restrict__ k_, const __half* __restrict__ v_,
              float* __restrict__ O)
{
    extern __shared__ __align__(16) char sm[];
    const uint32_t sb = smem_u32(sm);

    const int bh = blockIdx.y;
    const int b = bh >> 4, h = bh & 15;
    const int s0 = ((int)gridDim.x - 1 - (int)blockIdx.x) * 128;
    const int tid = threadIdx.x, wid = tid >> 5, lane = tid & 31;
    const int warp_m = wid * 16;
    const int g = lane >> 2, c2 = (lane & 3) * 2;

    const size_t qkb = (size_t)bh * Sq * DQK;
    const size_t vb  = (size_t)bh * Sq * DVq;

    const uint32_t a_off = (uint32_t)((warp_m + (lane & 15)) * QSTRB + ((lane >> 4) << 4));
    const uint32_t b_off = (uint32_t)(((lane & 7) + ((lane >> 4) << 3)) * QSTRB +
                                      (((lane >> 3) & 1) << 4));
    const uint32_t v_off = (uint32_t)((lane & 15) * VSTRB + ((lane >> 4) << 4));

    // ---- stage Q-hi (resident) and Q-lo (via K/V buffer area) ----
    {
        const __half* sh = qh_ + qkb + (size_t)s0 * DQK;
        const __half* sl = ql_ + qkb + (size_t)s0 * DQK;
#pragma unroll
        for (int j = 0; j < 12; j++) {
            int e = tid + j * 256;            // 0..3071
            int r = e / 24, s = e - r * 24;
            cp16(sb + r * QSTRB + s * 16, sh + r * 192 + s * 8);
            cp16(sb + KBUF0 + r * QSTRB + s * 16, sl + r * 192 + s * 8);
        }
        CP_COMMIT();
        CP_WAIT(0);
        __syncthreads();
    }

    // ---- Q-lo fragments -> registers (48 regs) ----
    uint32_t qlo[12][4];
#pragma unroll
    for (int ks = 0; ks < 12; ks++)
        ldm4(qlo[ks], sb + KBUF0 + a_off + ks * 32);
    __syncthreads();

    // ---- K/V tile loader (single fp16) ----
    auto load_kv = [&](int jb, int buf) {
        const uint32_t kb = sb + KBUF0 + buf * 25600;
        const uint32_t vbuf = sb + VBUF0 + buf * 17408;
        const __half* sk = k_ + qkb + (size_t)(jb * 64) * DQK;
        const __half* sv = v_ + vb + (size_t)(jb * 64) * DVq;
#pragma unroll
        for (int j = 0; j < 6; j++) {
            int e = tid + j * 256;            // 0..1535
            int r = e / 24, s = e - r * 24;
            cp16(kb + r * QSTRB + s * 16, sk + r * 192 + s * 8);
        }
#pragma unroll
        for (int j = 0; j < 4; j++) {
            int e = tid + j * 256;            // 0..1023
            int r = e >> 4, s = e & 15;
            cp16(vbuf + r * VSTRB + s * 16, sv + r * 128 + s * 8);
        }
        CP_COMMIT();
    };

    const int jmax = (s0 >> 6) + 1;
    load_kv(0, 0);

    float accO[16][4];
#pragma unroll
    for (int nf = 0; nf < 16; nf++)
#pragma unroll
        for (int j = 0; j < 4; j++) accO[nf][j] = 0.f;
    float m0 = -INFINITY, m1 = -INFINITY, l0 = 0.f, l1 = 0.f;

    const float scale = 0.07216878364870322f;   // 1/sqrt(192)
    const int row0 = s0 + warp_m + g;
    const int row1 = row0 + 8;

    for (int jb = 0; jb <= jmax; jb++) {
        const int buf = jb & 1;
        if (jb < jmax) {
            load_kv(jb + 1, buf ^ 1);
            CP_WAIT(1);
        } else {
            CP_WAIT(0);
        }
        __syncthreads();

        const uint32_t kb = sb + KBUF0 + buf * 25600;
        const uint32_t vbuf = sb + VBUF0 + buf * 17408;

        // ---- S = (Qhi + Qlo) K^T ----
        float S[8][4];
#pragma unroll
        for (int nf = 0; nf < 8; nf++)
#pragma unroll
            for (int j = 0; j < 4; j++) S[nf][j] = 0.f;

#pragma unroll
        for (int ks = 0; ks < 12; ks++) {
            uint32_t ah[4];
            ldm4(ah, sb + a_off + ks * 32);
#pragma unroll
            for (int p = 0; p < 4; p++) {
                uint32_t bv[4];
                ldm4(bv, kb + b_off + p * 16 * QSTRB + ks * 32);
                mma16816(S[2*p],   ah, bv);
                mma16816(S[2*p+1], ah, bv + 2);
                mma16816(S[2*p],   qlo[ks], bv);
                mma16816(S[2*p+1], qlo[ks], bv + 2);
            }
        }

        // ---- scale + causal mask ----
        const bool domask = ((jb << 6) + 63) > row0;
#pragma unroll
        for (int nf = 0; nf < 8; nf++) {
#pragma unroll
            for (int j = 0; j < 4; j++) S[nf][j] *= scale;
            if (domask) {
                int key0 = (jb << 6) + nf * 8 + c2;
                if (key0     > row0) S[nf][0] = -INFINITY;
                if (key0 + 1 > row0) S[nf][1] = -INFINITY;
                if (key0     > row1) S[nf][2] = -INFINITY;
                if (key0 + 1 > row1) S[nf][3] = -INFINITY;
            }
        }

        // ---- online softmax ----
        float rm0 = -INFINITY, rm1 = -INFINITY;
#pragma unroll
        for (int nf = 0; nf < 8; nf++) {
            rm0 = fmaxf(rm0, fmaxf(S[nf][0], S[nf][1]));
            rm1 = fmaxf(rm1, fmaxf(S[nf][2], S[nf][3]));
        }
        rm0 = fmaxf(rm0, __shfl_xor_sync(0xffffffffu, rm0, 1));
        rm0 = fmaxf(rm0, __shfl_xor_sync(0xffffffffu, rm0, 2));
        rm1 = fmaxf(rm1, __shfl_xor_sync(0xffffffffu, rm1, 1));
        rm1 = fmaxf(rm1, __shfl_xor_sync(0xffffffffu, rm1, 2));

        float mn0 = fmaxf(m0, rm0), mn1 = fmaxf(m1, rm1);
        float al0 = __expf(m0 - mn0), al1 = __expf(m1 - mn1);
        m0 = mn0; m1 = mn1;

        float rs0 = 0.f, rs1 = 0.f;
#pragma unroll
        for (int nf = 0; nf < 8; nf++) {
            S[nf][0] = __expf(S[nf][0] - mn0);
            S[nf][1] = __expf(S[nf][1] - mn0);
            S[nf][2] = __expf(S[nf][2] - mn1);
            S[nf][3] = __expf(S[nf][3] - mn1);
            rs0 += S[nf][0] + S[nf][1];
            rs1 += S[nf][2] + S[nf][3];
        }
        rs0 += __shfl_xor_sync(0xffffffffu, rs0, 1);
        rs0 += __shfl_xor_sync(0xffffffffu, rs0, 2);
        rs1 += __shfl_xor_sync(0xffffffffu, rs1, 1);
        rs1 += __shfl_xor_sync(0xffffffffu, rs1, 2);
        l0 = l0 * al0 + rs0;
        l1 = l1 * al1 + rs1;

#pragma unroll
        for (int nf = 0; nf < 16; nf++) {
            accO[nf][0] *= al0; accO[nf][1] *= al0;
            accO[nf][2] *= al1; accO[nf][3] *= al1;
        }

        // ---- pack P fragments (hi/lo) ----
        uint32_t ph[4][4], pl[4][4];
#pragma unroll
        for (int t = 0; t < 4; t++) {
            float v00 = S[2*t][0],   v01 = S[2*t][1];
            float v10 = S[2*t][2],   v11 = S[2*t][3];
            float v20 = S[2*t+1][0], v21 = S[2*t+1][1];
            float v30 = S[2*t+1][2], v31 = S[2*t+1][3];
            ph[t][0] = packh2(v00, v01);
            ph[t][1] = packh2(v10, v11);
            ph[t][2] = packh2(v20, v21);
            ph[t][3] = packh2(v30, v31);
            __half2 h0 = *(__half2*)&ph[t][0];
            __half2 h1 = *(__half2*)&ph[t][1];
            __half2 h2 = *(__half2*)&ph[t][2];
            __half2 h3 = *(__half2*)&ph[t][3];
            pl[t][0] = packh2(v00 - __low2float(h0), v01 - __high2float(h0));
            pl[t][1] = packh2(v10 - __low2float(h1), v11 - __high2float(h1));
            pl[t][2] = packh2(v20 - __low2float(h2), v21 - __high2float(h2));
            pl[t][3] = packh2(v30 - __low2float(h3), v31 - __high2float(h3));
        }

        // ---- O += (Phi + Plo) V ----
#pragma unroll
        for (int t = 0; t < 4; t++) {
#pragma unroll
            for (int p = 0; p < 8; p++) {
                uint32_t bv[4];
                ldm4t(bv, vbuf + v_off + t * 16 * VSTRB + p * 32);
                mma16816(accO[2*p],   ph[t], bv);
                mma16816(accO[2*p+1], ph[t], bv + 2);
                mma16816(accO[2*p],   pl[t], bv);
                mma16816(accO[2*p+1], pl[t], bv + 2);
            }
        }
        __syncthreads();
    }

    // ---- epilogue ----
    float inv0 = 1.0f / l0, inv1 = 1.0f / l1;
#pragma unroll
    for (int nf = 0; nf < 16; nf++) {
        int col = h * DVq + nf * 8 + c2;
        size_t o0 = ((size_t)(b * Sq + row0)) * (size_t)(Hq * DVq) + col;
        size_t o1 = ((size_t)(b * Sq + row1)) * (size_t)(Hq * DVq) + col;
        *(float2*)(O + o0) = make_float2(accO[nf][0] * inv0, accO[nf][1] * inv0);
        *(float2*)(O + o1) = make_float2(accO[nf][2] * inv1, accO[nf][3] * inv1);
    }
}

// ---------------------------------------------------------------------------
extern "C" void kernel_launch(void* const* d_in, const int* in_sizes, int n_in,
                              void* d_out, int out_size)
{
    (void)in_sizes; (void)n_in; (void)out_size;
    const float* x    = (const float*)d_in[0];
    const float* W_c  = (const float*)d_in[1];
    const float* W_cp = (const float*)d_in[2];
    const float* W_qc = (const float*)d_in[3];
    const float* W_qr = (const float*)d_in[4];
    const float* W_kc = (const float*)d_in[5];
    const float* W_kr = (const float*)d_in[6];
    const float* W_v  = (const float*)d_in[7];
    float* out = (float*)d_out;

    char* arena;
    cudaGetSymbolAddress((void**)&arena, g_arena);
    __half* xhi   = (__half*)(arena + O_XHI);
    __half* xlo   = (__half*)(arena + O_XLO);
    __half* WcT   = (__half*)(arena + O_WCT);
    __half* WcpT  = (__half*)(arena + O_WCPT);
    __half* WqcT  = (__half*)(arena + O_WQCT);
    __half* WqrT  = (__half*)(arena + O_WQRT);
    __half* WkcT  = (__half*)(arena + O_WKCT);
    __half* WkrT  = (__half*)(arena + O_WKRT);
    __half* WvT   = (__half*)(arena + O_WVT);
    __half* chi   = (__half*)(arena + O_CHI);
    __half* clo   = (__half*)(arena + O_CLO);
    __half* cphi  = (__half*)(arena + O_CPHI);
    __half* cplo  = (__half*)(arena + O_CPLO);
    __half* kr    = (__half*)(arena + O_KR);
    __half* qh    = (__half*)(arena + O_QH);
    __half* ql    = (__half*)(arena + O_QL);
    __half* ks    = (__half*)(arena + O_KS);
    __half* vs    = (__half*)(arena + O_VS);

    const int GSM128 = 2 * (2 * 10240 + 128 * 80);  // 61440
    const int GSM64  = 2 * (2 * 10240 +  64 * 80);  // 51200
    cudaFuncSetAttribute(mma_gemm<128>, cudaFuncAttributeMaxDynamicSharedMemorySize, GSM128);
    cudaFuncSetAttribute(mma_gemm<64>,  cudaFuncAttributeMaxDynamicSharedMemorySize, GSM64);
    cudaFuncSetAttribute(attn_mma, cudaFuncAttributeMaxDynamicSharedMemorySize, ATTN_SMEM);

    // x -> fp16 hi/lo split; weights -> transposed fp16 single
    split_f32<<<32768, 256>>>(x, xhi, xlo);
    tround<<<dim3(16, 64, 1),  dim3(32, 8)>>>(W_c,  WcT,  2048, 512);
    tround<<<dim3(32, 64, 1),  dim3(32, 8)>>>(W_cp, WcpT, 2048, 1024);
    tround<<<dim3( 4, 32, 16), dim3(32, 8)>>>(W_qc, WqcT, 1024, 128);
    tround<<<dim3( 2, 32, 16), dim3(32, 8)>>>(W_qr, WqrT, 1024, 64);
    tround<<<dim3( 4, 16, 16), dim3(32, 8)>>>(W_kc, WkcT, 512, 128);
    tround<<<dim3( 2, 64, 1),  dim3(32, 8)>>>(W_kr, WkrT, 2048, 64);
    tround<<<dim3( 4, 16, 16), dim3(32, 8)>>>(W_v,  WvT,  512, 128);

    // projections (fp16 2-term mma.sync)
    mma_gemm<128><<<dim3(4, 32, 1),  256, GSM128>>>(xhi, xlo, WcT, nullptr, chi, clo,
                                                    2048, 512, 2, 0, 0);
    mma_gemm<128><<<dim3(8, 32, 1),  256, GSM128>>>(xhi, xlo, WcpT, nullptr, cphi, cplo,
                                                    2048, 1024, 2, 0, 0);
    mma_gemm<64> <<<dim3(1, 32, 1),  256, GSM64 >>>(xhi, xlo, WkrT, kr, nullptr, nullptr,
                                                    2048, 64, 5, 0, 64);
    mma_gemm<128><<<dim3(1, 32, 16), 256, GSM128>>>(cphi, cplo, WqcT, nullptr, qh, ql,
                                                    1024, 128, 3, 0, DQK);
    mma_gemm<64> <<<dim3(1, 32, 16), 256, GSM64 >>>(cphi, cplo, WqrT, nullptr, qh, ql,
                                                    1024, 64, 3, 128, DQK);
    mma_gemm<128><<<dim3(1, 32, 16), 256, GSM128>>>(chi, clo, WkcT, ks, nullptr, nullptr,
                                                    512, 128, 4, 0, DQK);
    mma_gemm<128><<<dim3(1, 32, 16), 256, GSM128>>>(chi, clo, WvT, vs, nullptr, nullptr,
                                                    512, 128, 4, 0, DVq);

    bcast_k<<<(Bq*Hq*Sq*32) / 256, 256>>>((const uint32_t*)kr, (uint32_t*)ks);
    attn_mma<<<dim3(Sq / 128, Bq * Hq), 256, ATTN_SMEM>>>(qh, ql, ks, vs, out);
}

// round 8
// speedup vs baseline: 7.3805x; 1.1945x over previous
#include <cuda_runtime.h>
#include <cuda_fp16.h>
#include <math.h>
#include <stdint.h>

// Problem constants
#define Bq   2
#define Sq   2048
#define DIMq 2048
#define Hq   16
#define DKq  128
#define DRq  64
#define DCq  512
#define DCPq 1024
#define DVq  128
#define DQK  192
#define Mrows (Bq*Sq)      // 4096

// ------------------------- scratch arena (bss) ------------------------------
#define O_XHI    0ULL
#define O_XLO    16777216ULL
#define O_WCT    33554432ULL
#define O_WCPT   35651584ULL
#define O_WQT    39845888ULL      // packed [16][192][1024] (qc rows 0-127, qr 128-191)
#define O_WKVT   46137344ULL      // packed [16][256][512]  (kc rows 0-127, v 128-255)
#define O_WKRT   50331648ULL
#define O_CHI    50593792ULL
#define O_CLO    54788096ULL
#define O_CPHI   58982400ULL
#define O_CPLO   67371008ULL
#define O_KR     75759616ULL      // kr single fp16 [B,S,64]
#define O_QH     76283904ULL      // q single [B,H,S,192]
#define O_KS     101449728ULL     // k single [B,H,S,192]
#define O_VS     126615552ULL     // v single [B,H,S,128]
#define ARENA_BYTES 143392768ULL

__device__ __align__(256) char g_arena[ARENA_BYTES];

// ------------------------- helpers ------------------------------------------
__device__ __forceinline__ uint32_t smem_u32(const void* p) {
    uint32_t a;
    asm("{ .reg .u64 t; cvta.to.shared.u64 t, %1; cvt.u32.u64 %0, t; }" : "=r"(a) : "l"(p));
    return a;
}

__device__ __forceinline__ void cp16(uint32_t dst, const void* src) {
    asm volatile("cp.async.cg.shared.global [%0], [%1], 16;" :: "r"(dst), "l"(src));
}
#define CP_COMMIT() asm volatile("cp.async.commit_group;" ::: "memory")
#define CP_WAIT(n)  asm volatile("cp.async.wait_group %0;" :: "n"(n) : "memory")

__device__ __forceinline__ void ldm4(uint32_t* r, uint32_t addr) {
    asm volatile("ldmatrix.sync.aligned.m8n8.x4.shared.b16 {%0,%1,%2,%3}, [%4];"
                 : "=r"(r[0]), "=r"(r[1]), "=r"(r[2]), "=r"(r[3]) : "r"(addr));
}
__device__ __forceinline__ void ldm4t(uint32_t* r, uint32_t addr) {
    asm volatile("ldmatrix.sync.aligned.m8n8.x4.trans.shared.b16 {%0,%1,%2,%3}, [%4];"
                 : "=r"(r[0]), "=r"(r[1]), "=r"(r[2]), "=r"(r[3]) : "r"(addr));
}

__device__ __forceinline__ void mma16816(float* d, const uint32_t* a, const uint32_t* b) {
    asm volatile("mma.sync.aligned.m16n8k16.row.col.f32.f16.f16.f32 "
                 "{%0,%1,%2,%3}, {%4,%5,%6,%7}, {%8,%9}, {%0,%1,%2,%3};"
                 : "+f"(d[0]), "+f"(d[1]), "+f"(d[2]), "+f"(d[3])
                 : "r"(a[0]), "r"(a[1]), "r"(a[2]), "r"(a[3]), "r"(b[0]), "r"(b[1]));
}

__device__ __forceinline__ uint32_t packh2(float x, float y) {
    __half2 t = __floats2half2_rn(x, y);
    return *(uint32_t*)&t;
}

// ---------------------------------------------------------------------------
// split x fp32 -> fp16 hi/lo
// ---------------------------------------------------------------------------
__global__ __launch_bounds__(256)
void split_f32(const float* __restrict__ A, __half* __restrict__ hi,
               __half* __restrict__ lo)
{
    int i = blockIdx.x * 256 + threadIdx.x;
    float v = A[i];
    __half h = __float2half_rn(v);
    hi[i] = h;
    lo[i] = __float2half_rn(v - __half2float(h));
}

// ---------------------------------------------------------------------------
// One kernel for ALL weight transposes+roundings (8320 tiles of 32x32).
// Segments (tile ranges): c[0,1024) cp[1024,3072) qc[3072,5120) qr[5120,6144)
//                         kc[6144,7168) v[7168,8192) kr[8192,8320)
// qc/qr pack into WqT [16][192][1024]; kc/v pack into WkvT [16][256][512].
// ---------------------------------------------------------------------------
__device__ __forceinline__ void tr_tile(const float* __restrict__ W,
                                        __half* __restrict__ out,
                                        int K, int N, int bx, int by)
{
    __shared__ float t[32][33];
    const int k0 = by * 32, n0 = bx * 32;
    const int x = threadIdx.x & 31, y = threadIdx.x >> 5;
#pragma unroll
    for (int i = 0; i < 4; i++)
        t[y + 8*i][x] = W[(size_t)(k0 + y + 8*i) * N + n0 + x];
    __syncthreads();
#pragma unroll
    for (int i = 0; i < 4; i++)
        out[(size_t)(n0 + y + 8*i) * K + k0 + x] = __float2half_rn(t[x][y + 8*i]);
}

__global__ __launch_bounds__(256)
void tround_all(const float* __restrict__ W_c, const float* __restrict__ W_cp,
                const float* __restrict__ W_qc, const float* __restrict__ W_qr,
                const float* __restrict__ W_kc, const float* __restrict__ W_v,
                const float* __restrict__ W_kr,
                __half* __restrict__ WcT, __half* __restrict__ WcpT,
                __half* __restrict__ WqT, __half* __restrict__ WkvT,
                __half* __restrict__ WkrT)
{
    const int bid = blockIdx.x;
    if (bid < 1024) {                       // W_c: K=2048 N=512, nx=16
        tr_tile(W_c, WcT, 2048, 512, bid & 15, bid >> 4);
    } else if (bid < 3072) {                // W_cp: K=2048 N=1024, nx=32
        int l = bid - 1024;
        tr_tile(W_cp, WcpT, 2048, 1024, l & 31, l >> 5);
    } else if (bid < 5120) {                // W_qc: per-head 128 tiles, nx=4
        int l = bid - 3072;
        int h = l >> 7, rem = l & 127;
        tr_tile(W_qc + (size_t)h * 1024 * 128, WqT + (size_t)h * 192 * 1024,
                1024, 128, rem & 3, rem >> 2);
    } else if (bid < 6144) {                // W_qr: per-head 64 tiles, nx=2
        int l = bid - 5120;
        int h = l >> 6, rem = l & 63;
        tr_tile(W_qr + (size_t)h * 1024 * 64, WqT + (size_t)h * 192 * 1024 + 128 * 1024,
                1024, 64, rem & 1, rem >> 1);
    } else if (bid < 7168) {                // W_kc: per-head 64 tiles, nx=4
        int l = bid - 6144;
        int h = l >> 6, rem = l & 63;
        tr_tile(W_kc + (size_t)h * 512 * 128, WkvT + (size_t)h * 256 * 512,
                512, 128, rem & 3, rem >> 2);
    } else if (bid < 8192) {                // W_v: per-head 64 tiles, nx=4
        int l = bid - 7168;
        int h = l >> 6, rem = l & 63;
        tr_tile(W_v + (size_t)h * 512 * 128, WkvT + (size_t)h * 256 * 512 + 128 * 512,
                512, 128, rem & 3, rem >> 2);
    } else {                                // W_kr: K=2048 N=64, nx=2
        int l = bid - 8192;
        tr_tile(W_kr, WkrT, 2048, 64, l & 1, l >> 1);
    }
}

// ---------------------------------------------------------------------------
// mma.sync fp16 2-term GEMM: C = (Ahi+Alo) * W16. k=64 chunks, ROWB=144
// (conflict-free), double-buffered, occupancy 2.
// out_kind: 2 = fp16 hi/lo flat [M][Nfull]
//           4 = fp16 single per-head, out_ld stride, col_off
//           5 = fp16 single flat
//           6 = kv split: col<128 -> C1 (ld 192); col>=128 -> Chi (ld 128)
// ---------------------------------------------------------------------------
template<int BN>
__global__ __launch_bounds__(256, 2)
void mma_gemm(const __half* __restrict__ Ahi, const __half* __restrict__ Alo,
              const __half* __restrict__ Bw,
              __half* __restrict__ C1, __half* __restrict__ Chi,
              __half* __restrict__ Clo,
              int K, int Nfull, int out_kind, int col_off, int out_ld)
{
    constexpr int ROWB = 144;           // 128 B data + 16 B pad
    constexpr int ABUF = 128 * ROWB;    // 18432 B
    constexpr int BBUF = BN * ROWB;
    constexpr int BUFSZ = 2 * ABUF + BBUF;
    constexpr int BNW  = BN / 2;
    constexpr int NFR  = BNW / 8;

    extern __shared__ __align__(16) char smg[];

    const int tid  = threadIdx.x;
    const int wid  = tid >> 5;
    const int lane = tid & 31;
    const int m_blk = blockIdx.y * 128;
    const int n_blk = blockIdx.x * BN;
    const int head  = blockIdx.z;
    const int warp_m = (wid >> 1) * 32;
    const int warp_n = (wid & 1) * BNW;

    const __half* Bp = Bw + (size_t)head * (size_t)Nfull * (size_t)K;

    const uint32_t sb = smem_u32(smg);
    const int KC = K >> 6;

    float acc[2][NFR][4];
#pragma unroll
    for (int mi = 0; mi < 2; mi++)
#pragma unroll
        for (int ni = 0; ni < NFR; ni++)
#pragma unroll
            for (int j = 0; j < 4; j++) acc[mi][ni][j] = 0.f;

    auto load_chunk = [&](int i, int buf) {
        const int kt = i << 6;
        const uint32_t db = sb + buf * BUFSZ;
#pragma unroll
        for (int j = 0; j < 4; j++) {
            int e = tid + j * 256;          // 0..1023
            int r = e >> 3, s = e & 7;
            size_t g = (size_t)(m_blk + r) * K + kt + s * 8;
            cp16(db + r * ROWB + s * 16, Ahi + g);
            cp16(db + ABUF + r * ROWB + s * 16, Alo + g);
        }
#pragma unroll
        for (int j = 0; j < BN / 32; j++) {
            int e = tid + j * 256;
            int r = e >> 3, s = e & 7;
            cp16(db + 2 * ABUF + r * ROWB + s * 16,
                 Bp + (size_t)(n_blk + r) * K + kt + s * 8);
        }
        CP_COMMIT();
    };

    load_chunk(0, 0);

    const uint32_t aoff = (uint32_t)((warp_m + (lane & 15)) * ROWB + ((lane >> 4) << 4));
    const uint32_t boff = (uint32_t)((warp_n + (lane & 7) + ((lane >> 4) << 3)) * ROWB +
                                     (((lane >> 3) & 1) << 4));

    for (int i = 0; i < KC; i++) {
        const int buf = i & 1;
        if (i + 1 < KC) {
            load_chunk(i + 1, buf ^ 1);
            CP_WAIT(1);
        } else {
            CP_WAIT(0);
        }
        __syncthreads();

        const uint32_t db = sb + buf * BUFSZ;
#pragma unroll
        for (int ks = 0; ks < 4; ks++) {
            uint32_t ah[2][4], al[2][4];
#pragma unroll
            for (int mi = 0; mi < 2; mi++) {
                ldm4(ah[mi], db + aoff + mi * 16 * ROWB + ks * 32);
                ldm4(al[mi], db + ABUF + aoff + mi * 16 * ROWB + ks * 32);
            }
            uint32_t b[NFR][2];
#pragma unroll
            for (int nj = 0; nj < NFR / 2; nj++) {
                uint32_t r[4];
                ldm4(r, db + 2 * ABUF + boff + nj * 16 * ROWB + ks * 32);
                b[2*nj][0] = r[0]; b[2*nj][1] = r[1];
                b[2*nj+1][0] = r[2]; b[2*nj+1][1] = r[3];
            }
#pragma unroll
            for (int mi = 0; mi < 2; mi++)
#pragma unroll
                for (int ni = 0; ni < NFR; ni++) {
                    mma16816(acc[mi][ni], ah[mi], b[ni]);
                    mma16816(acc[mi][ni], al[mi], b[ni]);
                }
        }
        __syncthreads();
    }

    const int g = lane >> 2, c2 = (lane & 3) * 2;
#pragma unroll
    for (int mi = 0; mi < 2; mi++) {
#pragma unroll
        for (int ni = 0; ni < NFR; ni++) {
            int col = n_blk + warp_n + ni * 8 + c2;
#pragma unroll
            for (int hrow = 0; hrow < 2; hrow++) {
                int m = m_blk + warp_m + mi * 16 + g + hrow * 8;
                float v0 = acc[mi][ni][hrow * 2];
                float v1 = acc[mi][ni][hrow * 2 + 1];
                if (out_kind == 2) {
                    uint32_t hh = packh2(v0, v1);
                    __half2 h2 = *(__half2*)&hh;
                    uint32_t ll = packh2(v0 - __low2float(h2), v1 - __high2float(h2));
                    size_t o = (size_t)m * Nfull + col;
                    *(uint32_t*)(Chi + o) = hh;
                    *(uint32_t*)(Clo + o) = ll;
                } else if (out_kind == 4) {
                    int b = m >> 11, s = m & 2047;
                    size_t o = ((size_t)((b * Hq + head) * Sq + s)) * out_ld + col_off + col;
                    *(uint32_t*)(C1 + o) = packh2(v0, v1);
                } else if (out_kind == 6) {
                    int b = m >> 11, s = m & 2047;
                    size_t rowb = (size_t)((b * Hq + head) * Sq + s);
                    if (col < 128)
                        *(uint32_t*)(C1 + rowb * DQK + col) = packh2(v0, v1);
                    else
                        *(uint32_t*)(Chi + rowb * DVq + col - 128) = packh2(v0, v1);
                } else {   // 5
                    size_t o = (size_t)m * out_ld + col_off + col;
                    *(uint32_t*)(C1 + o) = packh2(v0, v1);
                }
            }
        }
    }
}

// ---------------------------------------------------------------------------
// Broadcast kr fp16 [B,S,64] into k [B,H,S,192] cols [128,192)
// ---------------------------------------------------------------------------
__global__ __launch_bounds__(256)
void bcast_k(const uint32_t* __restrict__ kr, uint32_t* __restrict__ k)
{
    int idx = blockIdx.x * 256 + threadIdx.x;   // B*H*S*32
    int j = idx & 31;
    int s = (idx >> 5) & 2047;
    int h = (idx >> 16) & 15;
    int b = idx >> 20;
    k[((size_t)((b * Hq + h) * Sq + s)) * 96 + 64 + j] = kr[(b * Sq + s) * 32 + j];
}

// ---------------------------------------------------------------------------
// Causal flash attention, fp16: S = Q.K (Q,K single fp16), O = (Phi+Plo).V.
// grid (S/128, B*H), 256 threads. Q resident smem; K/V double-buffered.
// ---------------------------------------------------------------------------
#define QSTRB 400   // 192 fp16 = 384 B + 16 pad
#define VSTRB 272   // 128 fp16 = 256 B + 16 pad
#define KBUF0 51200          // 2 x 25600 (K single)
#define VBUF0 102400         // 2 x 17408 (V single)
#define ATTN_SMEM 137216

__global__ __launch_bounds__(256, 1)
void attn_mma(const __half* __restrict__ q_,
              const __half* __restrict__ k_, const __half* __restrict__ v_,
              float* __restrict__ O)
{
    extern __shared__ __align__(16) char sm[];
    const uint32_t sb = smem_u32(sm);

    const int bh = blockIdx.y;
    const int b = bh >> 4, h = bh & 15;
    const int s0 = ((int)gridDim.x - 1 - (int)blockIdx.x) * 128;
    const int tid = threadIdx.x, wid = tid >> 5, lane = tid & 31;
    const int warp_m = wid * 16;
    const int g = lane >> 2, c2 = (lane & 3) * 2;

    const size_t qkb = (size_t)bh * Sq * DQK;
    const size_t vb  = (size_t)bh * Sq * DVq;

    const uint32_t a_off = (uint32_t)((warp_m + (lane & 15)) * QSTRB + ((lane >> 4) << 4));
    const uint32_t b_off = (uint32_t)(((lane & 7) + ((lane >> 4) << 3)) * QSTRB +
                                      (((lane >> 3) & 1) << 4));
    const uint32_t v_off = (uint32_t)((lane & 15) * VSTRB + ((lane >> 4) << 4));

    // ---- stage Q (resident) ----
    {
        const __half* sh = q_ + qkb + (size_t)s0 * DQK;
#pragma unroll
        for (int j = 0; j < 12; j++) {
            int e = tid + j * 256;            // 0..3071
            int r = e / 24, s = e - r * 24;
            cp16(sb + r * QSTRB + s * 16, sh + r * 192 + s * 8);
        }
        CP_COMMIT();
    }

    // ---- K/V tile loader ----
    auto load_kv = [&](int jb, int buf) {
        const uint32_t kb = sb + KBUF0 + buf * 25600;
        const uint32_t vbuf = sb + VBUF0 + buf * 17408;
        const __half* sk = k_ + qkb + (size_t)(jb * 64) * DQK;
        const __half* sv = v_ + vb + (size_t)(jb * 64) * DVq;
#pragma unroll
        for (int j = 0; j < 6; j++) {
            int e = tid + j * 256;            // 0..1535
            int r = e / 24, s = e - r * 24;
            cp16(kb + r * QSTRB + s * 16, sk + r * 192 + s * 8);
        }
#pragma unroll
        for (int j = 0; j < 4; j++) {
            int e = tid + j * 256;            // 0..1023
            int r = e >> 4, s = e & 15;
            cp16(vbuf + r * VSTRB + s * 16, sv + r * 128 + s * 8);
        }
        CP_COMMIT();
    };

    const int jmax = (s0 >> 6) + 1;
    load_kv(0, 0);

    float accO[16][4];
#pragma unroll
    for (int nf = 0; nf < 16; nf++)
#pragma unroll
        for (int j = 0; j < 4; j++) accO[nf][j] = 0.f;
    float m0 = -INFINITY, m1 = -INFINITY, l0 = 0.f, l1 = 0.f;

    const float scale = 0.07216878364870322f;   // 1/sqrt(192)
    const int row0 = s0 + warp_m + g;
    const int row1 = row0 + 8;

    for (int jb = 0; jb <= jmax; jb++) {
        const int buf = jb & 1;
        if (jb < jmax) {
            load_kv(jb + 1, buf ^ 1);
            CP_WAIT(1);
        } else {
            CP_WAIT(0);
        }
        __syncthreads();

        const uint32_t kb = sb + KBUF0 + buf * 25600;
        const uint32_t vbuf = sb + VBUF0 + buf * 17408;

        // ---- S = Q K^T ----
        float S[8][4];
#pragma unroll
        for (int nf = 0; nf < 8; nf++)
#pragma unroll
            for (int j = 0; j < 4; j++) S[nf][j] = 0.f;

#pragma unroll
        for (int ks = 0; ks < 12; ks++) {
            uint32_t ah[4];
            ldm4(ah, sb + a_off + ks * 32);
#pragma unroll
            for (int p = 0; p < 4; p++) {
                uint32_t bv[4];
                ldm4(bv, kb + b_off + p * 16 * QSTRB + ks * 32);
                mma16816(S[2*p],   ah, bv);
                mma16816(S[2*p+1], ah, bv + 2);
            }
        }

        // ---- scale + causal mask ----
        const bool domask = ((jb << 6) + 63) > row0;
#pragma unroll
        for (int nf = 0; nf < 8; nf++) {
#pragma unroll
            for (int j = 0; j < 4; j++) S[nf][j] *= scale;
            if (domask) {
                int key0 = (jb << 6) + nf * 8 + c2;
                if (key0     > row0) S[nf][0] = -INFINITY;
                if (key0 + 1 > row0) S[nf][1] = -INFINITY;
                if (key0     > row1) S[nf][2] = -INFINITY;
                if (key0 + 1 > row1) S[nf][3] = -INFINITY;
            }
        }

        // ---- online softmax ----
        float rm0 = -INFINITY, rm1 = -INFINITY;
#pragma unroll
        for (int nf = 0; nf < 8; nf++) {
            rm0 = fmaxf(rm0, fmaxf(S[nf][0], S[nf][1]));
            rm1 = fmaxf(rm1, fmaxf(S[nf][2], S[nf][3]));
        }
        rm0 = fmaxf(rm0, __shfl_xor_sync(0xffffffffu, rm0, 1));
        rm0 = fmaxf(rm0, __shfl_xor_sync(0xffffffffu, rm0, 2));
        rm1 = fmaxf(rm1, __shfl_xor_sync(0xffffffffu, rm1, 1));
        rm1 = fmaxf(rm1, __shfl_xor_sync(0xffffffffu, rm1, 2));

        float mn0 = fmaxf(m0, rm0), mn1 = fmaxf(m1, rm1);
        float al0 = __expf(m0 - mn0), al1 = __expf(m1 - mn1);
        m0 = mn0; m1 = mn1;

        float rs0 = 0.f, rs1 = 0.f;
#pragma unroll
        for (int nf = 0; nf < 8; nf++) {
            S[nf][0] = __expf(S[nf][0] - mn0);
            S[nf][1] = __expf(S[nf][1] - mn0);
            S[nf][2] = __expf(S[nf][2] - mn1);
            S[nf][3] = __expf(S[nf][3] - mn1);
            rs0 += S[nf][0] + S[nf][1];
            rs1 += S[nf][2] + S[nf][3];
        }
        rs0 += __shfl_xor_sync(0xffffffffu, rs0, 1);
        rs0 += __shfl_xor_sync(0xffffffffu, rs0, 2);
        rs1 += __shfl_xor_sync(0xffffffffu, rs1, 1);
        rs1 += __shfl_xor_sync(0xffffffffu, rs1, 2);
        l0 = l0 * al0 + rs0;
        l1 = l1 * al1 + rs1;

#pragma unroll
        for (int nf = 0; nf < 16; nf++) {
            accO[nf][0] *= al0; accO[nf][1] *= al0;
            accO[nf][2] *= al1; accO[nf][3] *= al1;
        }

        // ---- pack P fragments (hi/lo) ----
        uint32_t ph[4][4], pl[4][4];
#pragma unroll
        for (int t = 0; t < 4; t++) {
            float v00 = S[2*t][0],   v01 = S[2*t][1];
            float v10 = S[2*t][2],   v11 = S[2*t][3];
            float v20 = S[2*t+1][0], v21 = S[2*t+1][1];
            float v30 = S[2*t+1][2], v31 = S[2*t+1][3];
            ph[t][0] = packh2(v00, v01);
            ph[t][1] = packh2(v10, v11);
            ph[t][2] = packh2(v20, v21);
            ph[t][3] = packh2(v30, v31);
            __half2 h0 = *(__half2*)&ph[t][0];
            __half2 h1 = *(__half2*)&ph[t][1];
            __half2 h2 = *(__half2*)&ph[t][2];
            __half2 h3 = *(__half2*)&ph[t][3];
            pl[t][0] = packh2(v00 - __low2float(h0), v01 - __high2float(h0));
            pl[t][1] = packh2(v10 - __low2float(h1), v11 - __high2float(h1));
            pl[t][2] = packh2(v20 - __low2float(h2), v21 - __high2float(h2));
            pl[t][3] = packh2(v30 - __low2float(h3), v31 - __high2float(h3));
        }

        // ---- O += (Phi + Plo) V ----
#pragma unroll
        for (int t = 0; t < 4; t++) {
#pragma unroll
            for (int p = 0; p < 8; p++) {
                uint32_t bv[4];
                ldm4t(bv, vbuf + v_off + t * 16 * VSTRB + p * 32);
                mma16816(accO[2*p],   ph[t], bv);
                mma16816(accO[2*p+1], ph[t], bv + 2);
                mma16816(accO[2*p],   pl[t], bv);
                mma16816(accO[2*p+1], pl[t], bv + 2);
            }
        }
        __syncthreads();
    }

    // ---- epilogue ----
    float inv0 = 1.0f / l0, inv1 = 1.0f / l1;
#pragma unroll
    for (int nf = 0; nf < 16; nf++) {
        int col = h * DVq + nf * 8 + c2;
        size_t o0 = ((size_t)(b * Sq + row0)) * (size_t)(Hq * DVq) + col;
        size_t o1 = ((size_t)(b * Sq + row1)) * (size_t)(Hq * DVq) + col;
        *(float2*)(O + o0) = make_float2(accO[nf][0] * inv0, accO[nf][1] * inv0);
        *(float2*)(O + o1) = make_float2(accO[nf][2] * inv1, accO[nf][3] * inv1);
    }
}

// ---------------------------------------------------------------------------
extern "C" void kernel_launch(void* const* d_in, const int* in_sizes, int n_in,
                              void* d_out, int out_size)
{
    (void)in_sizes; (void)n_in; (void)out_size;
    const float* x    = (const float*)d_in[0];
    const float* W_c  = (const float*)d_in[1];
    const float* W_cp = (const float*)d_in[2];
    const float* W_qc = (const float*)d_in[3];
    const float* W_qr = (const float*)d_in[4];
    const float* W_kc = (const float*)d_in[5];
    const float* W_kr = (const float*)d_in[6];
    const float* W_v  = (const float*)d_in[7];
    float* out = (float*)d_out;

    char* arena;
    cudaGetSymbolAddress((void**)&arena, g_arena);
    __half* xhi   = (__half*)(arena + O_XHI);
    __half* xlo   = (__half*)(arena + O_XLO);
    __half* WcT   = (__half*)(arena + O_WCT);
    __half* WcpT  = (__half*)(arena + O_WCPT);
    __half* WqT   = (__half*)(arena + O_WQT);
    __half* WkvT  = (__half*)(arena + O_WKVT);
    __half* WkrT  = (__half*)(arena + O_WKRT);
    __half* chi   = (__half*)(arena + O_CHI);
    __half* clo   = (__half*)(arena + O_CLO);
    __half* cphi  = (__half*)(arena + O_CPHI);
    __half* cplo  = (__half*)(arena + O_CPLO);
    __half* kr    = (__half*)(arena + O_KR);
    __half* qh    = (__half*)(arena + O_QH);
    __half* ks    = (__half*)(arena + O_KS);
    __half* vs    = (__half*)(arena + O_VS);

    const int GSM128 = 2 * (2 * 18432 + 128 * 144);  // 110592
    const int GSM64  = 2 * (2 * 18432 +  64 * 144);  // 92160
    cudaFuncSetAttribute(mma_gemm<128>, cudaFuncAttributeMaxDynamicSharedMemorySize, GSM128);
    cudaFuncSetAttribute(mma_gemm<64>,  cudaFuncAttributeMaxDynamicSharedMemorySize, GSM64);
    cudaFuncSetAttribute(attn_mma, cudaFuncAttributeMaxDynamicSharedMemorySize, ATTN_SMEM);

    // prep: x split + all weight transposes in one kernel
    split_f32<<<32768, 256>>>(x, xhi, xlo);
    tround_all<<<8320, 256>>>(W_c, W_cp, W_qc, W_qr, W_kc, W_v, W_kr,
                              WcT, WcpT, WqT, WkvT, WkrT);

    // projections (fp16 2-term mma.sync, k=64 chunks)
    mma_gemm<128><<<dim3(4, 32, 1),  256, GSM128>>>(xhi, xlo, WcT, nullptr, chi, clo,
                                                    2048, 512, 2, 0, 0);
    mma_gemm<128><<<dim3(8, 32, 1),  256, GSM128>>>(xhi, xlo, WcpT, nullptr, cphi, cplo,
                                                    2048, 1024, 2, 0, 0);
    mma_gemm<64> <<<dim3(1, 32, 1),  256, GSM64 >>>(xhi, xlo, WkrT, kr, nullptr, nullptr,
                                                    2048, 64, 5, 0, 64);
    mma_gemm<64> <<<dim3(3, 32, 16), 256, GSM64 >>>(cphi, cplo, WqT, qh, nullptr, nullptr,
                                                    1024, 192, 4, 0, DQK);
    mma_gemm<128><<<dim3(2, 32, 16), 256, GSM128>>>(chi, clo, WkvT, ks, vs, nullptr,
                                                    512, 256, 6, 0, 0);

    bcast_k<<<(Bq*Hq*Sq*32) / 256, 256>>>((const uint32_t*)kr, (uint32_t*)ks);
    attn_mma<<<dim3(Sq / 128, Bq * Hq), 256, ATTN_SMEM>>>(qh, ks, vs, out);
}